// round 1
// baseline (speedup 1.0000x reference)
#include <cuda_runtime.h>
#include <math.h>

#define BATCH 2048
#define UNITS 768
#define IND   96
#define KTOT  864   /* IND + UNITS */
#define GATES 3072  /* 4*UNITS */
#define STEPS 64
#define TIN   24

// Persistent device scratch (no allocations allowed).
__device__ float g_xh[2][BATCH * KTOT];   // ping-pong [x(96) | h(768)] per batch row
__device__ float g_c[BATCH * UNITS];      // cell state (in-place update is race-free)
__device__ float g_Wcat[GATES * KTOT];    // [W_ih | W_hh] concat along K, row-major
__device__ float g_bsum[GATES];           // b_ih + b_hh

__device__ __forceinline__ float sigm(float x) { return 1.0f / (1.0f + expf(-x)); }

// ---------------------------------------------------------------------------
// Prep: build concatenated weights + fused bias (cheap; rerun every replay).
// ---------------------------------------------------------------------------
__global__ void prep_w(const float* __restrict__ W_ih, const float* __restrict__ W_hh,
                       const float* __restrict__ b_ih, const float* __restrict__ b_hh) {
    int i = blockIdx.x * blockDim.x + threadIdx.x;
    if (i < GATES * KTOT) {
        int r = i / KTOT, k = i % KTOT;
        g_Wcat[i] = (k < IND) ? W_ih[r * IND + k] : W_hh[r * UNITS + (k - IND)];
    }
    if (i < GATES) g_bsum[i] = b_ih[i] + b_hh[i];
}

// Prep: xh[0] = [inputs[:, -1, :] | 0], c = 0.
__global__ void prep_s(const float* __restrict__ inputs) {
    int i = blockIdx.x * blockDim.x + threadIdx.x;
    if (i < BATCH * KTOT) {
        int b = i / KTOT, k = i % KTOT;
        g_xh[0][i] = (k < IND) ? inputs[(b * TIN + (TIN - 1)) * IND + k] : 0.0f;
    }
    if (i < BATCH * UNITS) g_c[i] = 0.0f;
}

// ---------------------------------------------------------------------------
// Kernel 1: fused gates GEMM + LSTM cell.
//   gates[b, g*768+u] = dot(xh[p][b, :], Wcat[g*768+u, :]) + bsum
//   then cell -> c (in place), h -> xh[p^1] h-region.
// Tile: BM=64 batch x BU=32 units (=128 gate rows), BK=32. 256 threads.
// Each thread: 4 batch x 2 units x 4 gates = 32 accumulators.
// ---------------------------------------------------------------------------
#define BM 64
#define BU 32
#define BK 32

__global__ __launch_bounds__(256, 2) void step_gates(int p) {
    __shared__ __align__(16) float As[BK][68];    // [k][m], padded
    __shared__ __align__(16) float Bs[BK][128];   // [k][g*32+u]

    const float* __restrict__ X  = g_xh[p];
    float*       __restrict__ Ho = g_xh[p ^ 1];

    const int bm0 = blockIdx.x * BM;
    const int bu0 = blockIdx.y * BU;
    const int tid = threadIdx.x;
    const int tm  = tid & 15;   // -> 4 batch rows
    const int tn  = tid >> 4;   // -> 2 units

    float acc[4][2][4] = {};    // [gate][uu][mb]

    // B-load thread mapping (constant across k-tiles)
    const int p2   = tid & 127;
    const int bu   = p2 & 31;       // unit within tile
    const int bg   = p2 >> 5;       // gate index
    const int bkb  = (tid >> 7) * 16;
    const int brow = bg * UNITS + bu0 + bu;

    for (int k0 = 0; k0 < KTOT; k0 += BK) {
        // Load A tile (64x32) -> As[k][m], 2 float4 per thread, coalesced.
#pragma unroll
        for (int i = 0; i < 2; i++) {
            int idx = tid + i * 256;
            int kk4 = idx & 7, m = idx >> 3;
            float4 v = *(const float4*)&X[(bm0 + m) * KTOT + k0 + kk4 * 4];
            As[kk4 * 4 + 0][m] = v.x;
            As[kk4 * 4 + 1][m] = v.y;
            As[kk4 * 4 + 2][m] = v.z;
            As[kk4 * 4 + 3][m] = v.w;
        }
        // Load B tile (128 gate-rows x 32 k) -> Bs[k][g*32+u], 4 float4 per thread.
#pragma unroll
        for (int j = 0; j < 4; j++) {
            float4 v = *(const float4*)&g_Wcat[brow * KTOT + k0 + bkb + j * 4];
            Bs[bkb + j * 4 + 0][bg * 32 + bu] = v.x;
            Bs[bkb + j * 4 + 1][bg * 32 + bu] = v.y;
            Bs[bkb + j * 4 + 2][bg * 32 + bu] = v.z;
            Bs[bkb + j * 4 + 3][bg * 32 + bu] = v.w;
        }
        __syncthreads();

#pragma unroll 8
        for (int kk = 0; kk < BK; kk++) {
            float4 a = *(const float4*)&As[kk][tm * 4];
            float am[4] = {a.x, a.y, a.z, a.w};
#pragma unroll
            for (int g = 0; g < 4; g++) {
                float2 bb = *(const float2*)&Bs[kk][g * 32 + tn * 2];
#pragma unroll
                for (int mb = 0; mb < 4; mb++) {
                    acc[g][0][mb] += bb.x * am[mb];
                    acc[g][1][mb] += bb.y * am[mb];
                }
            }
        }
        __syncthreads();
    }

    // Fused LSTM cell epilogue.
#pragma unroll
    for (int uu = 0; uu < 2; uu++) {
        const int u = bu0 + tn * 2 + uu;
        const float bi = g_bsum[u];
        const float bf = g_bsum[UNITS + u];
        const float bg_ = g_bsum[2 * UNITS + u];
        const float bo = g_bsum[3 * UNITS + u];
#pragma unroll
        for (int mb = 0; mb < 4; mb++) {
            const int b = bm0 + tm * 4 + mb;
            float iv = sigm(acc[0][uu][mb] + bi);
            float fv = sigm(acc[1][uu][mb] + bf);
            float gv = tanhf(acc[2][uu][mb] + bg_);
            float ov = sigm(acc[3][uu][mb] + bo);
            float cc = fv * g_c[b * UNITS + u] + iv * gv;
            g_c[b * UNITS + u] = cc;
            Ho[b * KTOT + IND + u] = ov * tanhf(cc);
        }
    }
}

// ---------------------------------------------------------------------------
// Kernel 2: pred = h @ W_d^T + b_d; write to out[:, step, :] AND to the
// x-region of the next step's xh buffer (autoregressive feedback).
// Tile: PM=32 batch x full N=96, BK=32. 256 threads, 2x6 per thread.
// ---------------------------------------------------------------------------
#define PM 32

__global__ __launch_bounds__(256) void step_pred(int p, int step,
                                                 float* __restrict__ out,
                                                 const float* __restrict__ W_d,
                                                 const float* __restrict__ b_d) {
    __shared__ __align__(16) float As[32][36];
    __shared__ __align__(16) float Bs[32][100];

    const float* __restrict__ H  = g_xh[p ^ 1];  // h written by step_gates this step
    float*       __restrict__ Xo = g_xh[p ^ 1];  // x-region of same buffer

    const int bm0 = blockIdx.x * PM;
    const int tid = threadIdx.x;
    const int tm  = tid & 15;   // -> 2 batch rows
    const int tn  = tid >> 4;   // -> 6 output cols

    float acc[2][6] = {};

    for (int k0 = 0; k0 < UNITS; k0 += 32) {
        // A tile (32x32): 1 float4 per thread.
        {
            int kk4 = tid & 7, m = tid >> 3;  // m in 0..31
            float4 v = *(const float4*)&H[(bm0 + m) * KTOT + IND + k0 + kk4 * 4];
            As[kk4 * 4 + 0][m] = v.x;
            As[kk4 * 4 + 1][m] = v.y;
            As[kk4 * 4 + 2][m] = v.z;
            As[kk4 * 4 + 3][m] = v.w;
        }
        // B tile (96 x 32): 3 float4 per thread.
#pragma unroll
        for (int i = 0; i < 3; i++) {
            int idx = tid + i * 256;
            int n = idx >> 3, kk4 = idx & 7;
            float4 v = *(const float4*)&W_d[n * UNITS + k0 + kk4 * 4];
            Bs[kk4 * 4 + 0][n] = v.x;
            Bs[kk4 * 4 + 1][n] = v.y;
            Bs[kk4 * 4 + 2][n] = v.z;
            Bs[kk4 * 4 + 3][n] = v.w;
        }
        __syncthreads();

#pragma unroll 8
        for (int kk = 0; kk < 32; kk++) {
            float2 a = *(const float2*)&As[kk][tm * 2];
#pragma unroll
            for (int j = 0; j < 6; j++) {
                float bv = Bs[kk][tn * 6 + j];
                acc[0][j] += a.x * bv;
                acc[1][j] += a.y * bv;
            }
        }
        __syncthreads();
    }

#pragma unroll
    for (int mb = 0; mb < 2; mb++) {
        const int b = bm0 + tm * 2 + mb;
#pragma unroll
        for (int j = 0; j < 6; j++) {
            const int n = tn * 6 + j;
            float v = acc[mb][j] + b_d[n];
            out[(b * STEPS + step) * IND + n] = v;   // output[b, step, n]
            Xo[b * KTOT + n] = v;                    // feedback x for next step
        }
    }
}

// ---------------------------------------------------------------------------
// Inputs (metadata order): inputs, W_ih, W_hh, b_ih, b_hh, W_d, b_d
// ---------------------------------------------------------------------------
extern "C" void kernel_launch(void* const* d_in, const int* in_sizes, int n_in,
                              void* d_out, int out_size) {
    const float* inputs = (const float*)d_in[0];
    const float* W_ih   = (const float*)d_in[1];
    const float* W_hh   = (const float*)d_in[2];
    const float* b_ih   = (const float*)d_in[3];
    const float* b_hh   = (const float*)d_in[4];
    const float* W_d    = (const float*)d_in[5];
    const float* b_d    = (const float*)d_in[6];
    float* out = (float*)d_out;

    prep_w<<<(GATES * KTOT + 255) / 256, 256>>>(W_ih, W_hh, b_ih, b_hh);
    prep_s<<<(BATCH * KTOT + 255) / 256, 256>>>(inputs);

    dim3 g1(BATCH / BM, UNITS / BU);   // 32 x 24 = 768 blocks
    for (int s = 0; s < STEPS; s++) {
        int p = s & 1;
        step_gates<<<g1, 256>>>(p);
        step_pred<<<BATCH / PM, 256>>>(p, s, out, W_d, b_d);
    }
}

// round 2
// speedup vs baseline: 1.0004x; 1.0004x over previous
#include <cuda_runtime.h>
#include <math.h>

#define BATCH 2048
#define UNITS 768
#define IND   96
#define KTOT  864   /* IND + UNITS */
#define GATES 3072  /* 4*UNITS */
#define STEPS 64
#define TIN   24

// Persistent device scratch (no allocations allowed).
__device__ float g_xh[2][BATCH * KTOT];   // ping-pong [x(96) | h(768)] per batch row
__device__ float g_c[BATCH * UNITS];      // cell state (in-place update is race-free)
__device__ float g_Wcat[GATES * KTOT];    // [W_ih | W_hh] concat along K, row-major
__device__ float g_bsum[GATES];           // b_ih + b_hh

__device__ __forceinline__ float sigm(float x) { return 1.0f / (1.0f + expf(-x)); }

// ---------------------------------------------------------------------------
// Prep: build concatenated weights + fused bias (cheap; rerun every replay).
// ---------------------------------------------------------------------------
__global__ void prep_w(const float* __restrict__ W_ih, const float* __restrict__ W_hh,
                       const float* __restrict__ b_ih, const float* __restrict__ b_hh) {
    int i = blockIdx.x * blockDim.x + threadIdx.x;
    if (i < GATES * KTOT) {
        int r = i / KTOT, k = i % KTOT;
        g_Wcat[i] = (k < IND) ? W_ih[r * IND + k] : W_hh[r * UNITS + (k - IND)];
    }
    if (i < GATES) g_bsum[i] = b_ih[i] + b_hh[i];
}

// Prep: xh[0] = [inputs[:, -1, :] | 0], c = 0.
__global__ void prep_s(const float* __restrict__ inputs) {
    int i = blockIdx.x * blockDim.x + threadIdx.x;
    if (i < BATCH * KTOT) {
        int b = i / KTOT, k = i % KTOT;
        g_xh[0][i] = (k < IND) ? inputs[(b * TIN + (TIN - 1)) * IND + k] : 0.0f;
    }
    if (i < BATCH * UNITS) g_c[i] = 0.0f;
}

// ---------------------------------------------------------------------------
// Kernel 1: fused gates GEMM + LSTM cell.
//   gates[b, g*768+u] = dot(xh[p][b, :], Wcat[g*768+u, :]) + bsum
//   then cell -> c (in place), h -> xh[p^1] h-region.
// Tile: BM=64 batch x BU=32 units (=128 gate rows), BK=32. 256 threads.
// Each thread: 4 batch x 2 units x 4 gates = 32 accumulators.
// ---------------------------------------------------------------------------
#define BM 64
#define BU 32
#define BK 32

__global__ __launch_bounds__(256, 2) void step_gates(int p) {
    __shared__ __align__(16) float As[BK][68];    // [k][m], padded
    __shared__ __align__(16) float Bs[BK][128];   // [k][g*32+u]

    const float* __restrict__ X  = g_xh[p];
    float*       __restrict__ Ho = g_xh[p ^ 1];

    const int bm0 = blockIdx.x * BM;
    const int bu0 = blockIdx.y * BU;
    const int tid = threadIdx.x;
    const int tm  = tid & 15;   // -> 4 batch rows
    const int tn  = tid >> 4;   // -> 2 units

    float acc[4][2][4] = {};    // [gate][uu][mb]

    // B-load thread mapping (constant across k-tiles)
    const int p2   = tid & 127;
    const int bu   = p2 & 31;       // unit within tile
    const int bg   = p2 >> 5;       // gate index
    const int bkb  = (tid >> 7) * 16;
    const int brow = bg * UNITS + bu0 + bu;

    for (int k0 = 0; k0 < KTOT; k0 += BK) {
        // Load A tile (64x32) -> As[k][m], 2 float4 per thread, coalesced.
#pragma unroll
        for (int i = 0; i < 2; i++) {
            int idx = tid + i * 256;
            int kk4 = idx & 7, m = idx >> 3;
            float4 v = *(const float4*)&X[(bm0 + m) * KTOT + k0 + kk4 * 4];
            As[kk4 * 4 + 0][m] = v.x;
            As[kk4 * 4 + 1][m] = v.y;
            As[kk4 * 4 + 2][m] = v.z;
            As[kk4 * 4 + 3][m] = v.w;
        }
        // Load B tile (128 gate-rows x 32 k) -> Bs[k][g*32+u], 4 float4 per thread.
#pragma unroll
        for (int j = 0; j < 4; j++) {
            float4 v = *(const float4*)&g_Wcat[brow * KTOT + k0 + bkb + j * 4];
            Bs[bkb + j * 4 + 0][bg * 32 + bu] = v.x;
            Bs[bkb + j * 4 + 1][bg * 32 + bu] = v.y;
            Bs[bkb + j * 4 + 2][bg * 32 + bu] = v.z;
            Bs[bkb + j * 4 + 3][bg * 32 + bu] = v.w;
        }
        __syncthreads();

#pragma unroll 8
        for (int kk = 0; kk < BK; kk++) {
            float4 a = *(const float4*)&As[kk][tm * 4];
            float am[4] = {a.x, a.y, a.z, a.w};
#pragma unroll
            for (int g = 0; g < 4; g++) {
                float2 bb = *(const float2*)&Bs[kk][g * 32 + tn * 2];
#pragma unroll
                for (int mb = 0; mb < 4; mb++) {
                    acc[g][0][mb] += bb.x * am[mb];
                    acc[g][1][mb] += bb.y * am[mb];
                }
            }
        }
        __syncthreads();
    }

    // Fused LSTM cell epilogue.
#pragma unroll
    for (int uu = 0; uu < 2; uu++) {
        const int u = bu0 + tn * 2 + uu;
        const float bi = g_bsum[u];
        const float bf = g_bsum[UNITS + u];
        const float bg_ = g_bsum[2 * UNITS + u];
        const float bo = g_bsum[3 * UNITS + u];
#pragma unroll
        for (int mb = 0; mb < 4; mb++) {
            const int b = bm0 + tm * 4 + mb;
            float iv = sigm(acc[0][uu][mb] + bi);
            float fv = sigm(acc[1][uu][mb] + bf);
            float gv = tanhf(acc[2][uu][mb] + bg_);
            float ov = sigm(acc[3][uu][mb] + bo);
            float cc = fv * g_c[b * UNITS + u] + iv * gv;
            g_c[b * UNITS + u] = cc;
            Ho[b * KTOT + IND + u] = ov * tanhf(cc);
        }
    }
}

// ---------------------------------------------------------------------------
// Kernel 2: pred = h @ W_d^T + b_d; write to out[:, step, :] AND to the
// x-region of the next step's xh buffer (autoregressive feedback).
// Tile: PM=32 batch x full N=96, BK=32. 256 threads, 2x6 per thread.
// ---------------------------------------------------------------------------
#define PM 32

__global__ __launch_bounds__(256) void step_pred(int p, int step,
                                                 float* __restrict__ out,
                                                 const float* __restrict__ W_d,
                                                 const float* __restrict__ b_d) {
    __shared__ __align__(16) float As[32][36];
    __shared__ __align__(16) float Bs[32][100];

    const float* __restrict__ H  = g_xh[p ^ 1];  // h written by step_gates this step
    float*       __restrict__ Xo = g_xh[p ^ 1];  // x-region of same buffer

    const int bm0 = blockIdx.x * PM;
    const int tid = threadIdx.x;
    const int tm  = tid & 15;   // -> 2 batch rows
    const int tn  = tid >> 4;   // -> 6 output cols

    float acc[2][6] = {};

    for (int k0 = 0; k0 < UNITS; k0 += 32) {
        // A tile (32x32): 1 float4 per thread.
        {
            int kk4 = tid & 7, m = tid >> 3;  // m in 0..31
            float4 v = *(const float4*)&H[(bm0 + m) * KTOT + IND + k0 + kk4 * 4];
            As[kk4 * 4 + 0][m] = v.x;
            As[kk4 * 4 + 1][m] = v.y;
            As[kk4 * 4 + 2][m] = v.z;
            As[kk4 * 4 + 3][m] = v.w;
        }
        // B tile (96 x 32): 3 float4 per thread.
#pragma unroll
        for (int i = 0; i < 3; i++) {
            int idx = tid + i * 256;
            int n = idx >> 3, kk4 = idx & 7;
            float4 v = *(const float4*)&W_d[n * UNITS + k0 + kk4 * 4];
            Bs[kk4 * 4 + 0][n] = v.x;
            Bs[kk4 * 4 + 1][n] = v.y;
            Bs[kk4 * 4 + 2][n] = v.z;
            Bs[kk4 * 4 + 3][n] = v.w;
        }
        __syncthreads();

#pragma unroll 8
        for (int kk = 0; kk < 32; kk++) {
            float2 a = *(const float2*)&As[kk][tm * 2];
#pragma unroll
            for (int j = 0; j < 6; j++) {
                float bv = Bs[kk][tn * 6 + j];
                acc[0][j] += a.x * bv;
                acc[1][j] += a.y * bv;
            }
        }
        __syncthreads();
    }

#pragma unroll
    for (int mb = 0; mb < 2; mb++) {
        const int b = bm0 + tm * 2 + mb;
#pragma unroll
        for (int j = 0; j < 6; j++) {
            const int n = tn * 6 + j;
            float v = acc[mb][j] + b_d[n];
            out[(b * STEPS + step) * IND + n] = v;   // output[b, step, n]
            Xo[b * KTOT + n] = v;                    // feedback x for next step
        }
    }
}

// ---------------------------------------------------------------------------
// Inputs (metadata order): inputs, W_ih, W_hh, b_ih, b_hh, W_d, b_d
// ---------------------------------------------------------------------------
extern "C" void kernel_launch(void* const* d_in, const int* in_sizes, int n_in,
                              void* d_out, int out_size) {
    const float* inputs = (const float*)d_in[0];
    const float* W_ih   = (const float*)d_in[1];
    const float* W_hh   = (const float*)d_in[2];
    const float* b_ih   = (const float*)d_in[3];
    const float* b_hh   = (const float*)d_in[4];
    const float* W_d    = (const float*)d_in[5];
    const float* b_d    = (const float*)d_in[6];
    float* out = (float*)d_out;

    prep_w<<<(GATES * KTOT + 255) / 256, 256>>>(W_ih, W_hh, b_ih, b_hh);
    prep_s<<<(BATCH * KTOT + 255) / 256, 256>>>(inputs);

    dim3 g1(BATCH / BM, UNITS / BU);   // 32 x 24 = 768 blocks
    for (int s = 0; s < STEPS; s++) {
        int p = s & 1;
        step_gates<<<g1, 256>>>(p);
        step_pred<<<BATCH / PM, 256>>>(p, s, out, W_d, b_d);
    }
}

// round 4
// speedup vs baseline: 2.5087x; 2.5078x over previous
#include <cuda_runtime.h>
#include <cuda_fp16.h>
#include <cstdint>
#include <math.h>

#define BATCH 2048
#define UNITS 768
#define IND   96
#define KTOT  864
#define KPAD  896          /* padded to 14 x 64 */
#define GATES 3072
#define STEPS 64
#define TIN   24
#define NCH   14           /* K chunks of 64 halves */

#define MT 128
#define NTILE 128          /* 32 units x 4 gates (reorder r' = u*4+q) */
#define MTILES 16
#define NTILES 24

/* smem: 2 stages x 64KB (AH,AL,BH,BL tiles of 16KB each) + bias */
#define STG_STRIDE 65536
#define T_AH 0
#define T_AL 16384
#define T_BH 32768
#define T_BL 49152
#define OFF_BIAS 131072
#define GATES_SMEM (OFF_BIAS + 512)

// ---------------------------------------------------------------------------
// Device globals
// ---------------------------------------------------------------------------
__device__ __half g_Ahi[2][BATCH * KPAD];   // ping-pong [x(96)|h(768)|pad] hi
__device__ __half g_Alo[2][BATCH * KPAD];   // lo
__device__ float  g_h[BATCH * UNITS];       // full-precision h (pred input)
__device__ float  g_c[BATCH * UNITS];       // cell state
__device__ __half g_Whi[GATES * KPAD];      // reordered [Wih|Whh|pad] hi
__device__ __half g_Wlo[GATES * KPAD];      // lo
__device__ float  g_bsumr[GATES];           // reordered b_ih + b_hh

__device__ __forceinline__ uint32_t smem_u32(const void* p) {
    uint32_t a;
    asm("{ .reg .u64 t; cvta.to.shared.u64 t, %1; cvt.u32.u64 %0, t; }" : "=r"(a) : "l"(p));
    return a;
}
__device__ __forceinline__ void cp16(uint32_t dst, const void* src) {
    asm volatile("cp.async.cg.shared.global [%0], [%1], 16;" :: "r"(dst), "l"(src));
}
__device__ __forceinline__ void ldsm4(uint32_t* r, uint32_t addr) {
    asm volatile("ldmatrix.sync.aligned.m8n8.x4.shared.b16 {%0,%1,%2,%3}, [%4];"
        : "=r"(r[0]), "=r"(r[1]), "=r"(r[2]), "=r"(r[3]) : "r"(addr));
}
__device__ __forceinline__ void mma16816(float* c, const uint32_t* a, uint32_t b0, uint32_t b1) {
    asm volatile("mma.sync.aligned.m16n8k16.row.col.f32.f16.f16.f32 "
        "{%0,%1,%2,%3}, {%4,%5,%6,%7}, {%8,%9}, {%0,%1,%2,%3};"
        : "+f"(c[0]), "+f"(c[1]), "+f"(c[2]), "+f"(c[3])
        : "r"(a[0]), "r"(a[1]), "r"(a[2]), "r"(a[3]), "r"(b0), "r"(b1));
}
__device__ __forceinline__ float sigm(float x) { return 1.0f / (1.0f + expf(-x)); }

// ---------------------------------------------------------------------------
// prep: reordered + fp16-split weights. r' = u*4 + q  <->  orig q*768 + u.
// ---------------------------------------------------------------------------
__global__ void prep_w(const float* __restrict__ W_ih, const float* __restrict__ W_hh,
                       const float* __restrict__ b_ih, const float* __restrict__ b_hh) {
    int i = blockIdx.x * blockDim.x + threadIdx.x;
    if (i < GATES * KPAD) {
        int rp = i / KPAD, k = i % KPAD;
        int u = rp >> 2, q = rp & 3;
        int orig = q * UNITS + u;
        float w = 0.0f;
        if (k < IND)       w = W_ih[orig * IND + k];
        else if (k < KTOT) w = W_hh[orig * UNITS + (k - IND)];
        __half hi = __float2half_rn(w);
        g_Whi[i] = hi;
        g_Wlo[i] = __float2half_rn(w - __half2float(hi));
    }
    if (i < GATES) {
        int u = i >> 2, q = i & 3;
        g_bsumr[i] = b_ih[q * UNITS + u] + b_hh[q * UNITS + u];
    }
}

__global__ void prep_s(const float* __restrict__ inputs) {
    int i = blockIdx.x * blockDim.x + threadIdx.x;
    if (i < BATCH * KPAD) {
        int b = i / KPAD, k = i % KPAD;
        float v = (k < IND) ? inputs[(b * TIN + (TIN - 1)) * IND + k] : 0.0f;
        __half hi = __float2half_rn(v);
        g_Ahi[0][i] = hi;
        g_Alo[0][i] = __float2half_rn(v - __half2float(hi));
        g_Ahi[1][i] = __float2half_rn(0.0f);   // pad region must stay zero
        g_Alo[1][i] = __float2half_rn(0.0f);
    }
    if (i < BATCH * UNITS) g_c[i] = 0.0f;
}

// ---------------------------------------------------------------------------
// step_gates: fp16-split (3-product) mma.sync GEMM M=128,N=128,K=896
//             + fused LSTM cell epilogue.
// ---------------------------------------------------------------------------
__device__ __forceinline__ void load_stage(uint32_t sb, int stage, int kc, int tid,
                                           int bm0, int n0r,
                                           const __half* __restrict__ Ah,
                                           const __half* __restrict__ Al) {
    uint32_t base = sb + stage * STG_STRIDE;
    int k0 = kc * 64;   // halves
#pragma unroll
    for (int i = 0; i < 4; i++) {
        int e = tid + i * 256;
        int row = e >> 3, sub = e & 7;
        uint32_t off = row * 128 + sub * 16;
        uint32_t sw = off ^ ((off >> 3) & 0x70);
        size_t gA = (size_t)(bm0 + row) * KPAD + k0 + sub * 8;
        cp16(base + T_AH + sw, Ah + gA);
        cp16(base + T_AL + sw, Al + gA);
        size_t gB = (size_t)(n0r + row) * KPAD + k0 + sub * 8;
        cp16(base + T_BH + sw, g_Whi + gB);
        cp16(base + T_BL + sw, g_Wlo + gB);
    }
    asm volatile("cp.async.commit_group;");
}

__global__ __launch_bounds__(256, 1) void step_gates(int p) {
    extern __shared__ __align__(1024) char smem[];
    const uint32_t sb = smem_u32(smem);
    float* sB = (float*)(smem + OFF_BIAS);
    const int tid = threadIdx.x;
    const int wid = tid >> 5;
    const int lane = tid & 31;
    const int bm0 = blockIdx.x * MT;
    const int nt  = blockIdx.y;
    const int n0r = nt * NTILE;

    const __half* __restrict__ Ah = g_Ahi[p];
    const __half* __restrict__ Al = g_Alo[p];

    if (tid < NTILE) sB[tid] = g_bsumr[n0r + tid];

    // warp tiling: 2 (m) x 4 (n); warp tile 64 x 32
    const int wm = wid & 1, wn = wid >> 1;

    // ldmatrix lane addressing (relative to a [128 rows x 128B] tile)
    const int ra = lane & 7, qa = lane >> 3;
    const int colsel = (qa >> 1) * 16;        // 16B column within k16 block
    int arow[4], axor[4], browr[2], bxor[2];
#pragma unroll
    for (int mi = 0; mi < 4; mi++) {
        int r = wm * 64 + mi * 16 + ra + (qa & 1) * 8;
        arow[mi] = r * 128;
        axor[mi] = (r & 7) << 4;
    }
#pragma unroll
    for (int nb = 0; nb < 2; nb++) {
        int r = wn * 32 + nb * 16 + ra + (qa & 1) * 8;
        browr[nb] = r * 128;
        bxor[nb] = (r & 7) << 4;
    }

    float acc[4][4][4];
#pragma unroll
    for (int mi = 0; mi < 4; mi++)
#pragma unroll
        for (int ni = 0; ni < 4; ni++)
#pragma unroll
            for (int j = 0; j < 4; j++) acc[mi][ni][j] = 0.0f;

    load_stage(sb, 0, 0, tid, bm0, n0r, Ah, Al);

    int stage = 0;
#pragma unroll 1
    for (int i = 0; i < NCH; i++) {
        if (i + 1 < NCH) {
            load_stage(sb, stage ^ 1, i + 1, tid, bm0, n0r, Ah, Al);
            asm volatile("cp.async.wait_group 1;");
        } else {
            asm volatile("cp.async.wait_group 0;");
        }
        __syncthreads();

        uint32_t base = sb + stage * STG_STRIDE;
#pragma unroll
        for (int kk = 0; kk < 4; kk++) {
            const int colb = kk * 32 + colsel;
            uint32_t ah[4][4], al[4][4], bh[2][4], bl[2][4];
#pragma unroll
            for (int mi = 0; mi < 4; mi++) {
                ldsm4(ah[mi], base + T_AH + arow[mi] + (colb ^ axor[mi]));
                ldsm4(al[mi], base + T_AL + arow[mi] + (colb ^ axor[mi]));
            }
#pragma unroll
            for (int nb = 0; nb < 2; nb++) {
                ldsm4(bh[nb], base + T_BH + browr[nb] + (colb ^ bxor[nb]));
                ldsm4(bl[nb], base + T_BL + browr[nb] + (colb ^ bxor[nb]));
            }
#pragma unroll
            for (int mi = 0; mi < 4; mi++)
#pragma unroll
                for (int ni = 0; ni < 4; ni++) {
                    const int nb = ni >> 1, s = ni & 1;
                    mma16816(acc[mi][ni], ah[mi], bh[nb][s], bh[nb][s + 2]);
                    mma16816(acc[mi][ni], ah[mi], bl[nb][s], bl[nb][s + 2]);
                    mma16816(acc[mi][ni], al[mi], bh[nb][s], bh[nb][s + 2]);
                }
        }
        __syncthreads();
        stage ^= 1;
    }

    // ---- epilogue: frags -> smem, fused LSTM cell ----
    float* sC = (float*)smem;   // [128][132]
#pragma unroll
    for (int mi = 0; mi < 4; mi++)
#pragma unroll
        for (int ni = 0; ni < 4; ni++) {
            int r = wm * 64 + mi * 16 + (lane >> 2);
            int cidx = wn * 32 + ni * 8 + 2 * (lane & 3);
            sC[r * 132 + cidx]           = acc[mi][ni][0];
            sC[r * 132 + cidx + 1]       = acc[mi][ni][1];
            sC[(r + 8) * 132 + cidx]     = acc[mi][ni][2];
            sC[(r + 8) * 132 + cidx + 1] = acc[mi][ni][3];
        }
    __syncthreads();

    __half* __restrict__ nAh = g_Ahi[p ^ 1];
    __half* __restrict__ nAl = g_Alo[p ^ 1];
#pragma unroll
    for (int it = 0; it < 16; it++) {
        int idx = tid + it * 256;
        int row = idx >> 5, ul = idx & 31;
        int m = bm0 + row, ug = nt * 32 + ul;
        float iv = sigm(sC[row * 132 + ul * 4 + 0] + sB[ul * 4 + 0]);
        float fv = sigm(sC[row * 132 + ul * 4 + 1] + sB[ul * 4 + 1]);
        float gv = tanhf(sC[row * 132 + ul * 4 + 2] + sB[ul * 4 + 2]);
        float ov = sigm(sC[row * 132 + ul * 4 + 3] + sB[ul * 4 + 3]);
        float cv = fv * g_c[m * UNITS + ug] + iv * gv;
        g_c[m * UNITS + ug] = cv;
        float hv = ov * tanhf(cv);
        g_h[m * UNITS + ug] = hv;
        __half hi = __float2half_rn(hv);
        nAh[(size_t)m * KPAD + IND + ug] = hi;
        nAl[(size_t)m * KPAD + IND + ug] = __float2half_rn(hv - __half2float(hi));
    }
}

// ---------------------------------------------------------------------------
// step_pred: pred = h @ W_d^T + b_d -> out[:,step,:] + fp16-split feedback.
// ---------------------------------------------------------------------------
#define PM 16
__global__ __launch_bounds__(256) void step_pred(int p, int step,
                                                 float* __restrict__ out,
                                                 const float* __restrict__ W_d,
                                                 const float* __restrict__ b_d) {
    __shared__ __align__(16) float As[32][17];
    __shared__ __align__(16) float Bs[32][100];

    const int bm0 = blockIdx.x * PM;
    const int tid = threadIdx.x;
    const int tm = tid & 15;
    const int tn = tid >> 4;

    float acc[6] = {};

    for (int k0 = 0; k0 < UNITS; k0 += 32) {
        if (tid < 128) {
            int row = tid >> 3, k4 = tid & 7;
            float4 v = *(const float4*)&g_h[(bm0 + row) * UNITS + k0 + k4 * 4];
            As[k4 * 4 + 0][row] = v.x; As[k4 * 4 + 1][row] = v.y;
            As[k4 * 4 + 2][row] = v.z; As[k4 * 4 + 3][row] = v.w;
        }
#pragma unroll
        for (int i = 0; i < 3; i++) {
            int idx = tid + i * 256;
            int n = idx >> 3, k4 = idx & 7;
            float4 v = *(const float4*)&W_d[n * UNITS + k0 + k4 * 4];
            Bs[k4 * 4 + 0][n] = v.x; Bs[k4 * 4 + 1][n] = v.y;
            Bs[k4 * 4 + 2][n] = v.z; Bs[k4 * 4 + 3][n] = v.w;
        }
        __syncthreads();
#pragma unroll 8
        for (int kk = 0; kk < 32; kk++) {
            float a = As[kk][tm];
#pragma unroll
            for (int j = 0; j < 6; j++) acc[j] += a * Bs[kk][tn * 6 + j];
        }
        __syncthreads();
    }

    __half* __restrict__ nAh = g_Ahi[p ^ 1];
    __half* __restrict__ nAl = g_Alo[p ^ 1];
    const int b = bm0 + tm;
#pragma unroll
    for (int j = 0; j < 6; j++) {
        const int n = tn * 6 + j;
        float v = acc[j] + b_d[n];
        out[(b * STEPS + step) * IND + n] = v;
        __half hi = __float2half_rn(v);
        nAh[(size_t)b * KPAD + n] = hi;
        nAl[(size_t)b * KPAD + n] = __float2half_rn(v - __half2float(hi));
    }
}

// ---------------------------------------------------------------------------
// Inputs: inputs, W_ih, W_hh, b_ih, b_hh, W_d, b_d
// ---------------------------------------------------------------------------
extern "C" void kernel_launch(void* const* d_in, const int* in_sizes, int n_in,
                              void* d_out, int out_size) {
    const float* inputs = (const float*)d_in[0];
    const float* W_ih   = (const float*)d_in[1];
    const float* W_hh   = (const float*)d_in[2];
    const float* b_ih   = (const float*)d_in[3];
    const float* b_hh   = (const float*)d_in[4];
    const float* W_d    = (const float*)d_in[5];
    const float* b_d    = (const float*)d_in[6];
    float* out = (float*)d_out;

    cudaFuncSetAttribute(step_gates, cudaFuncAttributeMaxDynamicSharedMemorySize, GATES_SMEM);

    prep_w<<<(GATES * KPAD + 255) / 256, 256>>>(W_ih, W_hh, b_ih, b_hh);
    prep_s<<<(BATCH * KPAD + 255) / 256, 256>>>(inputs);

    dim3 gg(MTILES, NTILES);   // 16 x 24 = 384 CTAs
    for (int s = 0; s < STEPS; s++) {
        int p = s & 1;
        step_gates<<<gg, 256, GATES_SMEM>>>(p);
        step_pred<<<BATCH / PM, 256>>>(p, s, out, W_d, b_d);
    }
}

// round 5
// speedup vs baseline: 2.8872x; 1.1509x over previous
#include <cuda_runtime.h>
#include <cuda_fp16.h>
#include <cstdint>
#include <math.h>

#define BATCH 2048
#define UNITS 768
#define IND   96
#define KTOT  864
#define KPAD  896          /* padded to 14 x 64 */
#define GATES 3072
#define STEPS 64
#define TIN   24
#define NCH   14           /* K chunks of 64 halves */

#define MT 128
#define NTILE 128          /* 32 units x 4 gates (reorder r' = u*4+q) */
#define MTILES 16
#define NTILES 24

/* gates smem: 3 stages x 64KB (AH,AL,BH,BL tiles of 16KB each) + bias */
#define STG_STRIDE 65536
#define T_AH 0
#define T_AL 16384
#define T_BH 32768
#define T_BL 49152
#define OFF_BIAS 196608
#define GATES_SMEM (OFF_BIAS + 512)     /* 197120 */

/* pred smem: 2 stages x 56KB */
#define PSTG 57344
#define P_AH 0
#define P_AL 16384
#define P_BH 32768
#define P_BL 45056
#define PRED_SMEM (2 * PSTG)            /* 114688 */

// ---------------------------------------------------------------------------
// Device globals
// ---------------------------------------------------------------------------
__device__ __half g_Ahi[2][BATCH * KPAD];   // ping-pong [x(96)|h(768)|pad] hi
__device__ __half g_Alo[2][BATCH * KPAD];   // lo
__device__ float  g_c[BATCH * UNITS];       // cell state
__device__ __half g_Whi[GATES * KPAD];      // reordered [Wih|Whh|pad] hi
__device__ __half g_Wlo[GATES * KPAD];      // lo
__device__ __half g_Pdh[IND * UNITS];       // W_d hi (row n, col k)
__device__ __half g_Pdl[IND * UNITS];       // W_d lo
__device__ float  g_bsumr[GATES];           // reordered b_ih + b_hh
__device__ float  g_pp[4][BATCH * IND];     // pred split-K partials

__device__ __forceinline__ uint32_t smem_u32(const void* p) {
    uint32_t a;
    asm("{ .reg .u64 t; cvta.to.shared.u64 t, %1; cvt.u32.u64 %0, t; }" : "=r"(a) : "l"(p));
    return a;
}
__device__ __forceinline__ void cp16(uint32_t dst, const void* src) {
    asm volatile("cp.async.cg.shared.global [%0], [%1], 16;" :: "r"(dst), "l"(src));
}
__device__ __forceinline__ void ldsm4(uint32_t* r, uint32_t addr) {
    asm volatile("ldmatrix.sync.aligned.m8n8.x4.shared.b16 {%0,%1,%2,%3}, [%4];"
        : "=r"(r[0]), "=r"(r[1]), "=r"(r[2]), "=r"(r[3]) : "r"(addr));
}
__device__ __forceinline__ void mma16816(float* c, const uint32_t* a, uint32_t b0, uint32_t b1) {
    asm volatile("mma.sync.aligned.m16n8k16.row.col.f32.f16.f16.f32 "
        "{%0,%1,%2,%3}, {%4,%5,%6,%7}, {%8,%9}, {%0,%1,%2,%3};"
        : "+f"(c[0]), "+f"(c[1]), "+f"(c[2]), "+f"(c[3])
        : "r"(a[0]), "r"(a[1]), "r"(a[2]), "r"(a[3]), "r"(b0), "r"(b1));
}
__device__ __forceinline__ float sigm(float x) { return 1.0f / (1.0f + expf(-x)); }

// ---------------------------------------------------------------------------
// prep: reordered + fp16-split weights. r' = u*4 + q  <->  orig q*768 + u.
// Also split W_d.
// ---------------------------------------------------------------------------
__global__ void prep_w(const float* __restrict__ W_ih, const float* __restrict__ W_hh,
                       const float* __restrict__ b_ih, const float* __restrict__ b_hh,
                       const float* __restrict__ W_d) {
    int i = blockIdx.x * blockDim.x + threadIdx.x;
    if (i < GATES * KPAD) {
        int rp = i / KPAD, k = i % KPAD;
        int u = rp >> 2, q = rp & 3;
        int orig = q * UNITS + u;
        float w = 0.0f;
        if (k < IND)       w = W_ih[orig * IND + k];
        else if (k < KTOT) w = W_hh[orig * UNITS + (k - IND)];
        __half hi = __float2half_rn(w);
        g_Whi[i] = hi;
        g_Wlo[i] = __float2half_rn(w - __half2float(hi));
    }
    if (i < GATES) {
        int u = i >> 2, q = i & 3;
        g_bsumr[i] = b_ih[q * UNITS + u] + b_hh[q * UNITS + u];
    }
    if (i < IND * UNITS) {
        float w = W_d[i];
        __half hi = __float2half_rn(w);
        g_Pdh[i] = hi;
        g_Pdl[i] = __float2half_rn(w - __half2float(hi));
    }
}

__global__ void prep_s(const float* __restrict__ inputs) {
    int i = blockIdx.x * blockDim.x + threadIdx.x;
    if (i < BATCH * KPAD) {
        int b = i / KPAD, k = i % KPAD;
        float v = (k < IND) ? inputs[(b * TIN + (TIN - 1)) * IND + k] : 0.0f;
        __half hi = __float2half_rn(v);
        g_Ahi[0][i] = hi;
        g_Alo[0][i] = __float2half_rn(v - __half2float(hi));
        g_Ahi[1][i] = __float2half_rn(0.0f);   // pad region must stay zero
        g_Alo[1][i] = __float2half_rn(0.0f);
    }
    if (i < BATCH * UNITS) g_c[i] = 0.0f;
}

// ---------------------------------------------------------------------------
// step_gates: fp16-split (3-product) mma.sync GEMM M=128,N=128,K=896
//             + fused LSTM cell epilogue. 3-stage cp.async pipeline.
// ---------------------------------------------------------------------------
__device__ __forceinline__ void load_stage(uint32_t sb, int stage, int kc, int tid,
                                           int bm0, int n0r,
                                           const __half* __restrict__ Ah,
                                           const __half* __restrict__ Al) {
    uint32_t base = sb + stage * STG_STRIDE;
    int k0 = kc * 64;   // halves
#pragma unroll
    for (int i = 0; i < 4; i++) {
        int e = tid + i * 256;
        int row = e >> 3, sub = e & 7;
        uint32_t off = row * 128 + sub * 16;
        uint32_t sw = off ^ ((off >> 3) & 0x70);
        size_t gA = (size_t)(bm0 + row) * KPAD + k0 + sub * 8;
        cp16(base + T_AH + sw, Ah + gA);
        cp16(base + T_AL + sw, Al + gA);
        size_t gB = (size_t)(n0r + row) * KPAD + k0 + sub * 8;
        cp16(base + T_BH + sw, g_Whi + gB);
        cp16(base + T_BL + sw, g_Wlo + gB);
    }
    asm volatile("cp.async.commit_group;");
}

__global__ __launch_bounds__(256, 1) void step_gates(int p) {
    extern __shared__ __align__(1024) char smem[];
    const uint32_t sb = smem_u32(smem);
    float* sB = (float*)(smem + OFF_BIAS);
    const int tid = threadIdx.x;
    const int wid = tid >> 5;
    const int lane = tid & 31;
    const int bm0 = blockIdx.x * MT;
    const int nt  = blockIdx.y;
    const int n0r = nt * NTILE;

    const __half* __restrict__ Ah = g_Ahi[p];
    const __half* __restrict__ Al = g_Alo[p];

    if (tid < NTILE) sB[tid] = g_bsumr[n0r + tid];

    // warp tiling: 2 (m) x 4 (n); warp tile 64 x 32
    const int wm = wid & 1, wn = wid >> 1;

    const int ra = lane & 7, qa = lane >> 3;
    const int colsel = (qa >> 1) * 16;
    int arow[4], axor[4], browr[2], bxor[2];
#pragma unroll
    for (int mi = 0; mi < 4; mi++) {
        int r = wm * 64 + mi * 16 + ra + (qa & 1) * 8;
        arow[mi] = r * 128;
        axor[mi] = (r & 7) << 4;
    }
#pragma unroll
    for (int nb = 0; nb < 2; nb++) {
        int r = wn * 32 + nb * 16 + ra + (qa & 1) * 8;
        browr[nb] = r * 128;
        bxor[nb] = (r & 7) << 4;
    }

    float acc[4][4][4];
#pragma unroll
    for (int mi = 0; mi < 4; mi++)
#pragma unroll
        for (int ni = 0; ni < 4; ni++)
#pragma unroll
            for (int j = 0; j < 4; j++) acc[mi][ni][j] = 0.0f;

    load_stage(sb, 0, 0, tid, bm0, n0r, Ah, Al);
    load_stage(sb, 1, 1, tid, bm0, n0r, Ah, Al);

#pragma unroll 1
    for (int i = 0; i < NCH; i++) {
        if (i + 2 < NCH) {
            load_stage(sb, (i + 2) % 3, i + 2, tid, bm0, n0r, Ah, Al);
            asm volatile("cp.async.wait_group 2;");
        } else if (i + 1 < NCH) {
            asm volatile("cp.async.wait_group 1;");
        } else {
            asm volatile("cp.async.wait_group 0;");
        }
        __syncthreads();

        uint32_t base = sb + (i % 3) * STG_STRIDE;
#pragma unroll
        for (int kk = 0; kk < 4; kk++) {
            const int colb = kk * 32 + colsel;
            uint32_t ah[4][4], al[4][4], bh[2][4], bl[2][4];
#pragma unroll
            for (int mi = 0; mi < 4; mi++) {
                ldsm4(ah[mi], base + T_AH + arow[mi] + (colb ^ axor[mi]));
                ldsm4(al[mi], base + T_AL + arow[mi] + (colb ^ axor[mi]));
            }
#pragma unroll
            for (int nb = 0; nb < 2; nb++) {
                ldsm4(bh[nb], base + T_BH + browr[nb] + (colb ^ bxor[nb]));
                ldsm4(bl[nb], base + T_BL + browr[nb] + (colb ^ bxor[nb]));
            }
            // pass hh: 16 independent accumulators
#pragma unroll
            for (int mi = 0; mi < 4; mi++)
#pragma unroll
                for (int ni = 0; ni < 4; ni++) {
                    const int nb = ni >> 1, s = ni & 1;
                    mma16816(acc[mi][ni], ah[mi], bh[nb][s], bh[nb][s + 2]);
                }
            // pass hl
#pragma unroll
            for (int mi = 0; mi < 4; mi++)
#pragma unroll
                for (int ni = 0; ni < 4; ni++) {
                    const int nb = ni >> 1, s = ni & 1;
                    mma16816(acc[mi][ni], ah[mi], bl[nb][s], bl[nb][s + 2]);
                }
            // pass lh
#pragma unroll
            for (int mi = 0; mi < 4; mi++)
#pragma unroll
                for (int ni = 0; ni < 4; ni++) {
                    const int nb = ni >> 1, s = ni & 1;
                    mma16816(acc[mi][ni], al[mi], bh[nb][s], bh[nb][s + 2]);
                }
        }
        __syncthreads();
    }

    // ---- epilogue: frags -> smem, fused LSTM cell ----
    float* sC = (float*)smem;   // [128][132]
#pragma unroll
    for (int mi = 0; mi < 4; mi++)
#pragma unroll
        for (int ni = 0; ni < 4; ni++) {
            int r = wm * 64 + mi * 16 + (lane >> 2);
            int cidx = wn * 32 + ni * 8 + 2 * (lane & 3);
            sC[r * 132 + cidx]           = acc[mi][ni][0];
            sC[r * 132 + cidx + 1]       = acc[mi][ni][1];
            sC[(r + 8) * 132 + cidx]     = acc[mi][ni][2];
            sC[(r + 8) * 132 + cidx + 1] = acc[mi][ni][3];
        }
    __syncthreads();

    __half* __restrict__ nAh = g_Ahi[p ^ 1];
    __half* __restrict__ nAl = g_Alo[p ^ 1];
#pragma unroll
    for (int it = 0; it < 16; it++) {
        int idx = tid + it * 256;
        int row = idx >> 5, ul = idx & 31;
        int m = bm0 + row, ug = nt * 32 + ul;
        float iv = sigm(sC[row * 132 + ul * 4 + 0] + sB[ul * 4 + 0]);
        float fv = sigm(sC[row * 132 + ul * 4 + 1] + sB[ul * 4 + 1]);
        float gv = tanhf(sC[row * 132 + ul * 4 + 2] + sB[ul * 4 + 2]);
        float ov = sigm(sC[row * 132 + ul * 4 + 3] + sB[ul * 4 + 3]);
        float cv = fv * g_c[m * UNITS + ug] + iv * gv;
        g_c[m * UNITS + ug] = cv;
        float hv = ov * tanhf(cv);
        __half hi = __float2half_rn(hv);
        nAh[(size_t)m * KPAD + IND + ug] = hi;
        nAl[(size_t)m * KPAD + IND + ug] = __float2half_rn(hv - __half2float(hi));
    }
}

// ---------------------------------------------------------------------------
// step_predpart: split-K tensor GEMM. pred_partial = h @ W_d^T over K-slice.
// Grid (16 M-tiles, 4 K-slices). CTA: M=128, N=96, K=192 (3 chunks of 64).
// h is read as fp16 hi/lo from the A buffer written by step_gates.
// ---------------------------------------------------------------------------
__device__ __forceinline__ void load_pstage(uint32_t sb, int stage, int kq, int c,
                                            int tid, int bm0,
                                            const __half* __restrict__ Ah,
                                            const __half* __restrict__ Al) {
    uint32_t base = sb + stage * PSTG;
    int k0 = kq * 192 + c * 64;
#pragma unroll
    for (int i = 0; i < 4; i++) {      // A: 128 rows
        int e = tid + i * 256;
        int row = e >> 3, sub = e & 7;
        uint32_t off = row * 128 + sub * 16;
        uint32_t sw = off ^ ((off >> 3) & 0x70);
        size_t gA = (size_t)(bm0 + row) * KPAD + IND + k0 + sub * 8;
        cp16(base + P_AH + sw, Ah + gA);
        cp16(base + P_AL + sw, Al + gA);
    }
#pragma unroll
    for (int i = 0; i < 3; i++) {      // B: 96 rows
        int e = tid + i * 256;
        int row = e >> 3, sub = e & 7;
        uint32_t off = row * 128 + sub * 16;
        uint32_t sw = off ^ ((off >> 3) & 0x70);
        size_t gB = (size_t)row * UNITS + k0 + sub * 8;
        cp16(base + P_BH + sw, g_Pdh + gB);
        cp16(base + P_BL + sw, g_Pdl + gB);
    }
    asm volatile("cp.async.commit_group;");
}

__global__ __launch_bounds__(256, 1) void step_predpart(int p) {
    extern __shared__ __align__(1024) char smem[];
    const uint32_t sb = smem_u32(smem);
    const int tid = threadIdx.x;
    const int wid = tid >> 5;
    const int lane = tid & 31;
    const int bm0 = blockIdx.x * MT;
    const int kq  = blockIdx.y;

    const __half* __restrict__ Ah = g_Ahi[p ^ 1];
    const __half* __restrict__ Al = g_Alo[p ^ 1];

    // warp tiling: 4 (m) x 2 (n); warp tile 32 x 48
    const int wm = wid & 3, wn = wid >> 2;

    const int ra = lane & 7, qa = lane >> 3;
    const int colsel = (qa >> 1) * 16;
    int arow[2], axor[2], browr[3], bxor[3];
#pragma unroll
    for (int mi = 0; mi < 2; mi++) {
        int r = wm * 32 + mi * 16 + ra + (qa & 1) * 8;
        arow[mi] = r * 128;
        axor[mi] = (r & 7) << 4;
    }
#pragma unroll
    for (int nb = 0; nb < 3; nb++) {
        int r = wn * 48 + nb * 16 + ra + (qa & 1) * 8;
        browr[nb] = r * 128;
        bxor[nb] = (r & 7) << 4;
    }

    float acc[2][6][4];
#pragma unroll
    for (int mi = 0; mi < 2; mi++)
#pragma unroll
        for (int nj = 0; nj < 6; nj++)
#pragma unroll
            for (int j = 0; j < 4; j++) acc[mi][nj][j] = 0.0f;

    load_pstage(sb, 0, kq, 0, tid, bm0, Ah, Al);

    int stage = 0;
#pragma unroll 1
    for (int c = 0; c < 3; c++) {
        if (c + 1 < 3) {
            load_pstage(sb, stage ^ 1, kq, c + 1, tid, bm0, Ah, Al);
            asm volatile("cp.async.wait_group 1;");
        } else {
            asm volatile("cp.async.wait_group 0;");
        }
        __syncthreads();

        uint32_t base = sb + stage * PSTG;
#pragma unroll
        for (int kk = 0; kk < 4; kk++) {
            const int colb = kk * 32 + colsel;
            uint32_t ah[2][4], al[2][4], bh[3][4], bl[3][4];
#pragma unroll
            for (int mi = 0; mi < 2; mi++) {
                ldsm4(ah[mi], base + P_AH + arow[mi] + (colb ^ axor[mi]));
                ldsm4(al[mi], base + P_AL + arow[mi] + (colb ^ axor[mi]));
            }
#pragma unroll
            for (int nb = 0; nb < 3; nb++) {
                ldsm4(bh[nb], base + P_BH + browr[nb] + (colb ^ bxor[nb]));
                ldsm4(bl[nb], base + P_BL + browr[nb] + (colb ^ bxor[nb]));
            }
#pragma unroll
            for (int mi = 0; mi < 2; mi++)
#pragma unroll
                for (int nj = 0; nj < 6; nj++) {
                    const int nb = nj >> 1, s = nj & 1;
                    mma16816(acc[mi][nj], ah[mi], bh[nb][s], bh[nb][s + 2]);
                }
#pragma unroll
            for (int mi = 0; mi < 2; mi++)
#pragma unroll
                for (int nj = 0; nj < 6; nj++) {
                    const int nb = nj >> 1, s = nj & 1;
                    mma16816(acc[mi][nj], ah[mi], bl[nb][s], bl[nb][s + 2]);
                }
#pragma unroll
            for (int mi = 0; mi < 2; mi++)
#pragma unroll
                for (int nj = 0; nj < 6; nj++) {
                    const int nb = nj >> 1, s = nj & 1;
                    mma16816(acc[mi][nj], al[mi], bh[nb][s], bh[nb][s + 2]);
                }
        }
        __syncthreads();
        stage ^= 1;
    }

    // write partials
    float* pp = g_pp[kq];
#pragma unroll
    for (int mi = 0; mi < 2; mi++)
#pragma unroll
        for (int nj = 0; nj < 6; nj++) {
            int r = bm0 + wm * 32 + mi * 16 + (lane >> 2);
            int cidx = wn * 48 + nj * 8 + 2 * (lane & 3);
            *(float2*)&pp[r * IND + cidx] =
                make_float2(acc[mi][nj][0], acc[mi][nj][1]);
            *(float2*)&pp[(r + 8) * IND + cidx] =
                make_float2(acc[mi][nj][2], acc[mi][nj][3]);
        }
}

// ---------------------------------------------------------------------------
// step_predred: sum split-K partials, add bias, write output + feedback x.
// ---------------------------------------------------------------------------
__global__ __launch_bounds__(256) void step_predred(int p, int step,
                                                    float* __restrict__ out,
                                                    const float* __restrict__ b_d) {
    int idx = blockIdx.x * 256 + threadIdx.x;   // 2048*96 total
    int b = idx / IND, n = idx % IND;
    float v = g_pp[0][idx] + g_pp[1][idx] + g_pp[2][idx] + g_pp[3][idx] + b_d[n];
    out[(b * STEPS + step) * IND + n] = v;
    __half hi = __float2half_rn(v);
    g_Ahi[p ^ 1][(size_t)b * KPAD + n] = hi;
    g_Alo[p ^ 1][(size_t)b * KPAD + n] = __float2half_rn(v - __half2float(hi));
}

// ---------------------------------------------------------------------------
// Inputs: inputs, W_ih, W_hh, b_ih, b_hh, W_d, b_d
// ---------------------------------------------------------------------------
extern "C" void kernel_launch(void* const* d_in, const int* in_sizes, int n_in,
                              void* d_out, int out_size) {
    const float* inputs = (const float*)d_in[0];
    const float* W_ih   = (const float*)d_in[1];
    const float* W_hh   = (const float*)d_in[2];
    const float* b_ih   = (const float*)d_in[3];
    const float* b_hh   = (const float*)d_in[4];
    const float* W_d    = (const float*)d_in[5];
    const float* b_d    = (const float*)d_in[6];
    float* out = (float*)d_out;

    cudaFuncSetAttribute(step_gates, cudaFuncAttributeMaxDynamicSharedMemorySize, GATES_SMEM);
    cudaFuncSetAttribute(step_predpart, cudaFuncAttributeMaxDynamicSharedMemorySize, PRED_SMEM);

    prep_w<<<(GATES * KPAD + 255) / 256, 256>>>(W_ih, W_hh, b_ih, b_hh, W_d);
    prep_s<<<(BATCH * KPAD + 255) / 256, 256>>>(inputs);

    dim3 gg(MTILES, NTILES);   // 16 x 24 = 384 CTAs
    dim3 gp(MTILES, 4);        // 16 x 4  = 64 CTAs
    for (int s = 0; s < STEPS; s++) {
        int p = s & 1;
        step_gates<<<gg, 256, GATES_SMEM>>>(p);
        step_predpart<<<gp, 256, PRED_SMEM>>>(p);
        step_predred<<<(BATCH * IND) / 256, 256>>>(p, s, out, b_d);
    }
}

// round 6
// speedup vs baseline: 3.0072x; 1.0416x over previous
#include <cuda_runtime.h>
#include <cuda_fp16.h>
#include <cstdint>
#include <math.h>

#define BATCH 2048
#define UNITS 768
#define IND   96
#define KTOT  864
#define KPAD  896          /* padded to 14 x 64 */
#define GATES 3072
#define STEPS 64
#define TIN   24
#define NCH   14           /* K chunks of 64 halves */

#define MT 128
#define NTILE 128          /* 32 units x 4 gates (reorder r' = u*4+q) */
#define MTILES 16
#define NTILES 24

/* gates smem: 3 stages x 64KB (AH,AL,BH,BL tiles of 16KB each) + bias */
#define STG_STRIDE 65536
#define T_AH 0
#define T_AL 16384
#define T_BH 32768
#define T_BL 49152
#define OFF_BIAS 196608
#define GATES_SMEM (OFF_BIAS + 512)     /* 197120 */

/* pred smem: 2 stages x 56KB */
#define PSTG 57344
#define P_AH 0
#define P_AL 16384
#define P_BH 32768
#define P_BL 45056
#define PRED_SMEM (2 * PSTG)            /* 114688 */

// ---------------------------------------------------------------------------
// Device globals
// ---------------------------------------------------------------------------
__device__ __half g_Ahi[2][BATCH * KPAD];   // ping-pong [x(96)|h(768)|pad] hi
__device__ __half g_Alo[2][BATCH * KPAD];   // lo
__device__ float  g_c[BATCH * UNITS];       // cell state
__device__ __half g_Whi[GATES * KPAD];      // reordered [Wih|Whh|pad] hi
__device__ __half g_Wlo[GATES * KPAD];      // lo
__device__ __half g_Pdh[IND * UNITS];       // W_d hi (row n, col k)
__device__ __half g_Pdl[IND * UNITS];       // W_d lo
__device__ float  g_bsumr[GATES];           // reordered b_ih + b_hh
__device__ float  g_pp[4][BATCH * IND];     // pred split-K partials

__device__ __forceinline__ uint32_t smem_u32(const void* p) {
    uint32_t a;
    asm("{ .reg .u64 t; cvta.to.shared.u64 t, %1; cvt.u32.u64 %0, t; }" : "=r"(a) : "l"(p));
    return a;
}
__device__ __forceinline__ void cp16(uint32_t dst, const void* src) {
    asm volatile("cp.async.cg.shared.global [%0], [%1], 16;" :: "r"(dst), "l"(src));
}
__device__ __forceinline__ void ldsm4(uint32_t* r, uint32_t addr) {
    asm volatile("ldmatrix.sync.aligned.m8n8.x4.shared.b16 {%0,%1,%2,%3}, [%4];"
        : "=r"(r[0]), "=r"(r[1]), "=r"(r[2]), "=r"(r[3]) : "r"(addr));
}
__device__ __forceinline__ void mma16816(float* c, const uint32_t* a, uint32_t b0, uint32_t b1) {
    asm volatile("mma.sync.aligned.m16n8k16.row.col.f32.f16.f16.f32 "
        "{%0,%1,%2,%3}, {%4,%5,%6,%7}, {%8,%9}, {%0,%1,%2,%3};"
        : "+f"(c[0]), "+f"(c[1]), "+f"(c[2]), "+f"(c[3])
        : "r"(a[0]), "r"(a[1]), "r"(a[2]), "r"(a[3]), "r"(b0), "r"(b1));
}
// fp16-accumulate variant (2x rate on split-rate tensor pipes)
__device__ __forceinline__ void mma16816h(uint32_t* c, const uint32_t* a, uint32_t b0, uint32_t b1) {
    asm volatile("mma.sync.aligned.m16n8k16.row.col.f16.f16.f16.f16 "
        "{%0,%1}, {%2,%3,%4,%5}, {%6,%7}, {%0,%1};"
        : "+r"(c[0]), "+r"(c[1])
        : "r"(a[0]), "r"(a[1]), "r"(a[2]), "r"(a[3]), "r"(b0), "r"(b1));
}
__device__ __forceinline__ float sigm(float x) { return 1.0f / (1.0f + expf(-x)); }

// ---------------------------------------------------------------------------
// prep: reordered + fp16-split weights. r' = u*4 + q  <->  orig q*768 + u.
// ---------------------------------------------------------------------------
__global__ void prep_w(const float* __restrict__ W_ih, const float* __restrict__ W_hh,
                       const float* __restrict__ b_ih, const float* __restrict__ b_hh,
                       const float* __restrict__ W_d) {
    int i = blockIdx.x * blockDim.x + threadIdx.x;
    if (i < GATES * KPAD) {
        int rp = i / KPAD, k = i % KPAD;
        int u = rp >> 2, q = rp & 3;
        int orig = q * UNITS + u;
        float w = 0.0f;
        if (k < IND)       w = W_ih[orig * IND + k];
        else if (k < KTOT) w = W_hh[orig * UNITS + (k - IND)];
        __half hi = __float2half_rn(w);
        g_Whi[i] = hi;
        g_Wlo[i] = __float2half_rn(w - __half2float(hi));
    }
    if (i < GATES) {
        int u = i >> 2, q = i & 3;
        g_bsumr[i] = b_ih[q * UNITS + u] + b_hh[q * UNITS + u];
    }
    if (i < IND * UNITS) {
        float w = W_d[i];
        __half hi = __float2half_rn(w);
        g_Pdh[i] = hi;
        g_Pdl[i] = __float2half_rn(w - __half2float(hi));
    }
}

__global__ void prep_s(const float* __restrict__ inputs) {
    int i = blockIdx.x * blockDim.x + threadIdx.x;
    if (i < BATCH * KPAD) {
        int b = i / KPAD, k = i % KPAD;
        float v = (k < IND) ? inputs[(b * TIN + (TIN - 1)) * IND + k] : 0.0f;
        __half hi = __float2half_rn(v);
        g_Ahi[0][i] = hi;
        g_Alo[0][i] = __float2half_rn(v - __half2float(hi));
        g_Ahi[1][i] = __float2half_rn(0.0f);   // pad region must stay zero
        g_Alo[1][i] = __float2half_rn(0.0f);
    }
    if (i < BATCH * UNITS) g_c[i] = 0.0f;
}

// ---------------------------------------------------------------------------
// step_gates: fp16-split mma.sync GEMM M=128,N=128,K=896 + fused LSTM cell.
// hh pass: f32 accumulate. hl + lh cross passes: f16 accumulate (2x rate),
// folded into the f32 accumulators in the epilogue.
// ---------------------------------------------------------------------------
__device__ __forceinline__ void load_stage(uint32_t sb, int stage, int kc, int tid,
                                           int bm0, int n0r,
                                           const __half* __restrict__ Ah,
                                           const __half* __restrict__ Al) {
    uint32_t base = sb + stage * STG_STRIDE;
    int k0 = kc * 64;   // halves
#pragma unroll
    for (int i = 0; i < 4; i++) {
        int e = tid + i * 256;
        int row = e >> 3, sub = e & 7;
        uint32_t off = row * 128 + sub * 16;
        uint32_t sw = off ^ ((off >> 3) & 0x70);
        size_t gA = (size_t)(bm0 + row) * KPAD + k0 + sub * 8;
        cp16(base + T_AH + sw, Ah + gA);
        cp16(base + T_AL + sw, Al + gA);
        size_t gB = (size_t)(n0r + row) * KPAD + k0 + sub * 8;
        cp16(base + T_BH + sw, g_Whi + gB);
        cp16(base + T_BL + sw, g_Wlo + gB);
    }
    asm volatile("cp.async.commit_group;");
}

__global__ __launch_bounds__(256, 1) void step_gates(int p) {
    extern __shared__ __align__(1024) char smem[];
    const uint32_t sb = smem_u32(smem);
    float* sB = (float*)(smem + OFF_BIAS);
    const int tid = threadIdx.x;
    const int wid = tid >> 5;
    const int lane = tid & 31;
    const int bm0 = blockIdx.x * MT;
    const int nt  = blockIdx.y;
    const int n0r = nt * NTILE;

    const __half* __restrict__ Ah = g_Ahi[p];
    const __half* __restrict__ Al = g_Alo[p];

    if (tid < NTILE) sB[tid] = g_bsumr[n0r + tid];

    // warp tiling: 2 (m) x 4 (n); warp tile 64 x 32
    const int wm = wid & 1, wn = wid >> 1;

    const int ra = lane & 7, qa = lane >> 3;
    const int colsel = (qa >> 1) * 16;
    int arow[4], axor[4], browr[2], bxor[2];
#pragma unroll
    for (int mi = 0; mi < 4; mi++) {
        int r = wm * 64 + mi * 16 + ra + (qa & 1) * 8;
        arow[mi] = r * 128;
        axor[mi] = (r & 7) << 4;
    }
#pragma unroll
    for (int nb = 0; nb < 2; nb++) {
        int r = wn * 32 + nb * 16 + ra + (qa & 1) * 8;
        browr[nb] = r * 128;
        bxor[nb] = (r & 7) << 4;
    }

    float acc[4][4][4];
    uint32_t acc16[4][4][2];   // f16 accumulators for cross terms
#pragma unroll
    for (int mi = 0; mi < 4; mi++)
#pragma unroll
        for (int ni = 0; ni < 4; ni++) {
#pragma unroll
            for (int j = 0; j < 4; j++) acc[mi][ni][j] = 0.0f;
            acc16[mi][ni][0] = 0u;
            acc16[mi][ni][1] = 0u;
        }

    load_stage(sb, 0, 0, tid, bm0, n0r, Ah, Al);
    load_stage(sb, 1, 1, tid, bm0, n0r, Ah, Al);

#pragma unroll 1
    for (int i = 0; i < NCH; i++) {
        if (i + 2 < NCH) {
            load_stage(sb, (i + 2) % 3, i + 2, tid, bm0, n0r, Ah, Al);
            asm volatile("cp.async.wait_group 2;");
        } else if (i + 1 < NCH) {
            asm volatile("cp.async.wait_group 1;");
        } else {
            asm volatile("cp.async.wait_group 0;");
        }
        __syncthreads();

        uint32_t base = sb + (i % 3) * STG_STRIDE;
#pragma unroll
        for (int kk = 0; kk < 4; kk++) {
            const int colb = kk * 32 + colsel;
            uint32_t ah[4][4], al[4][4], bh[2][4], bl[2][4];
#pragma unroll
            for (int mi = 0; mi < 4; mi++) {
                ldsm4(ah[mi], base + T_AH + arow[mi] + (colb ^ axor[mi]));
                ldsm4(al[mi], base + T_AL + arow[mi] + (colb ^ axor[mi]));
            }
#pragma unroll
            for (int nb = 0; nb < 2; nb++) {
                ldsm4(bh[nb], base + T_BH + browr[nb] + (colb ^ bxor[nb]));
                ldsm4(bl[nb], base + T_BL + browr[nb] + (colb ^ bxor[nb]));
            }
            // pass hh: f32 accumulate (16 independent accumulators)
#pragma unroll
            for (int mi = 0; mi < 4; mi++)
#pragma unroll
                for (int ni = 0; ni < 4; ni++) {
                    const int nb = ni >> 1, s = ni & 1;
                    mma16816(acc[mi][ni], ah[mi], bh[nb][s], bh[nb][s + 2]);
                }
            // pass hl: f16 accumulate
#pragma unroll
            for (int mi = 0; mi < 4; mi++)
#pragma unroll
                for (int ni = 0; ni < 4; ni++) {
                    const int nb = ni >> 1, s = ni & 1;
                    mma16816h(acc16[mi][ni], ah[mi], bl[nb][s], bl[nb][s + 2]);
                }
            // pass lh: f16 accumulate
#pragma unroll
            for (int mi = 0; mi < 4; mi++)
#pragma unroll
                for (int ni = 0; ni < 4; ni++) {
                    const int nb = ni >> 1, s = ni & 1;
                    mma16816h(acc16[mi][ni], al[mi], bh[nb][s], bh[nb][s + 2]);
                }
        }
        __syncthreads();
    }

    // fold f16 cross accumulators into f32 accumulators
#pragma unroll
    for (int mi = 0; mi < 4; mi++)
#pragma unroll
        for (int ni = 0; ni < 4; ni++) {
            float2 c0 = __half22float2(*(__half2*)&acc16[mi][ni][0]);
            float2 c1 = __half22float2(*(__half2*)&acc16[mi][ni][1]);
            acc[mi][ni][0] += c0.x;
            acc[mi][ni][1] += c0.y;
            acc[mi][ni][2] += c1.x;
            acc[mi][ni][3] += c1.y;
        }

    // ---- epilogue: frags -> smem, fused LSTM cell ----
    float* sC = (float*)smem;   // [128][132]
#pragma unroll
    for (int mi = 0; mi < 4; mi++)
#pragma unroll
        for (int ni = 0; ni < 4; ni++) {
            int r = wm * 64 + mi * 16 + (lane >> 2);
            int cidx = wn * 32 + ni * 8 + 2 * (lane & 3);
            sC[r * 132 + cidx]           = acc[mi][ni][0];
            sC[r * 132 + cidx + 1]       = acc[mi][ni][1];
            sC[(r + 8) * 132 + cidx]     = acc[mi][ni][2];
            sC[(r + 8) * 132 + cidx + 1] = acc[mi][ni][3];
        }
    __syncthreads();

    __half* __restrict__ nAh = g_Ahi[p ^ 1];
    __half* __restrict__ nAl = g_Alo[p ^ 1];
#pragma unroll
    for (int it = 0; it < 16; it++) {
        int idx = tid + it * 256;
        int row = idx >> 5, ul = idx & 31;
        int m = bm0 + row, ug = nt * 32 + ul;
        float iv = sigm(sC[row * 132 + ul * 4 + 0] + sB[ul * 4 + 0]);
        float fv = sigm(sC[row * 132 + ul * 4 + 1] + sB[ul * 4 + 1]);
        float gv = tanhf(sC[row * 132 + ul * 4 + 2] + sB[ul * 4 + 2]);
        float ov = sigm(sC[row * 132 + ul * 4 + 3] + sB[ul * 4 + 3]);
        float cv = fv * g_c[m * UNITS + ug] + iv * gv;
        g_c[m * UNITS + ug] = cv;
        float hv = ov * tanhf(cv);
        __half hi = __float2half_rn(hv);
        nAh[(size_t)m * KPAD + IND + ug] = hi;
        nAl[(size_t)m * KPAD + IND + ug] = __float2half_rn(hv - __half2float(hi));
    }
}

// ---------------------------------------------------------------------------
// step_predpart: split-K tensor GEMM. pred_partial = h @ W_d^T over K-slice.
// Grid (16 M-tiles, 4 K-slices). CTA: M=128, N=96, K=192 (3 chunks of 64).
// ---------------------------------------------------------------------------
__device__ __forceinline__ void load_pstage(uint32_t sb, int stage, int kq, int c,
                                            int tid, int bm0,
                                            const __half* __restrict__ Ah,
                                            const __half* __restrict__ Al) {
    uint32_t base = sb + stage * PSTG;
    int k0 = kq * 192 + c * 64;
#pragma unroll
    for (int i = 0; i < 4; i++) {      // A: 128 rows
        int e = tid + i * 256;
        int row = e >> 3, sub = e & 7;
        uint32_t off = row * 128 + sub * 16;
        uint32_t sw = off ^ ((off >> 3) & 0x70);
        size_t gA = (size_t)(bm0 + row) * KPAD + IND + k0 + sub * 8;
        cp16(base + P_AH + sw, Ah + gA);
        cp16(base + P_AL + sw, Al + gA);
    }
#pragma unroll
    for (int i = 0; i < 3; i++) {      // B: 96 rows
        int e = tid + i * 256;
        int row = e >> 3, sub = e & 7;
        uint32_t off = row * 128 + sub * 16;
        uint32_t sw = off ^ ((off >> 3) & 0x70);
        size_t gB = (size_t)row * UNITS + k0 + sub * 8;
        cp16(base + P_BH + sw, g_Pdh + gB);
        cp16(base + P_BL + sw, g_Pdl + gB);
    }
    asm volatile("cp.async.commit_group;");
}

__global__ __launch_bounds__(256, 1) void step_predpart(int p) {
    extern __shared__ __align__(1024) char smem[];
    const uint32_t sb = smem_u32(smem);
    const int tid = threadIdx.x;
    const int wid = tid >> 5;
    const int lane = tid & 31;
    const int bm0 = blockIdx.x * MT;
    const int kq  = blockIdx.y;

    const __half* __restrict__ Ah = g_Ahi[p ^ 1];
    const __half* __restrict__ Al = g_Alo[p ^ 1];

    // warp tiling: 4 (m) x 2 (n); warp tile 32 x 48
    const int wm = wid & 3, wn = wid >> 2;

    const int ra = lane & 7, qa = lane >> 3;
    const int colsel = (qa >> 1) * 16;
    int arow[2], axor[2], browr[3], bxor[3];
#pragma unroll
    for (int mi = 0; mi < 2; mi++) {
        int r = wm * 32 + mi * 16 + ra + (qa & 1) * 8;
        arow[mi] = r * 128;
        axor[mi] = (r & 7) << 4;
    }
#pragma unroll
    for (int nb = 0; nb < 3; nb++) {
        int r = wn * 48 + nb * 16 + ra + (qa & 1) * 8;
        browr[nb] = r * 128;
        bxor[nb] = (r & 7) << 4;
    }

    float acc[2][6][4];
#pragma unroll
    for (int mi = 0; mi < 2; mi++)
#pragma unroll
        for (int nj = 0; nj < 6; nj++)
#pragma unroll
            for (int j = 0; j < 4; j++) acc[mi][nj][j] = 0.0f;

    load_pstage(sb, 0, kq, 0, tid, bm0, Ah, Al);

    int stage = 0;
#pragma unroll 1
    for (int c = 0; c < 3; c++) {
        if (c + 1 < 3) {
            load_pstage(sb, stage ^ 1, kq, c + 1, tid, bm0, Ah, Al);
            asm volatile("cp.async.wait_group 1;");
        } else {
            asm volatile("cp.async.wait_group 0;");
        }
        __syncthreads();

        uint32_t base = sb + stage * PSTG;
#pragma unroll
        for (int kk = 0; kk < 4; kk++) {
            const int colb = kk * 32 + colsel;
            uint32_t ah[2][4], al[2][4], bh[3][4], bl[3][4];
#pragma unroll
            for (int mi = 0; mi < 2; mi++) {
                ldsm4(ah[mi], base + P_AH + arow[mi] + (colb ^ axor[mi]));
                ldsm4(al[mi], base + P_AL + arow[mi] + (colb ^ axor[mi]));
            }
#pragma unroll
            for (int nb = 0; nb < 3; nb++) {
                ldsm4(bh[nb], base + P_BH + browr[nb] + (colb ^ bxor[nb]));
                ldsm4(bl[nb], base + P_BL + browr[nb] + (colb ^ bxor[nb]));
            }
#pragma unroll
            for (int mi = 0; mi < 2; mi++)
#pragma unroll
                for (int nj = 0; nj < 6; nj++) {
                    const int nb = nj >> 1, s = nj & 1;
                    mma16816(acc[mi][nj], ah[mi], bh[nb][s], bh[nb][s + 2]);
                }
#pragma unroll
            for (int mi = 0; mi < 2; mi++)
#pragma unroll
                for (int nj = 0; nj < 6; nj++) {
                    const int nb = nj >> 1, s = nj & 1;
                    mma16816(acc[mi][nj], ah[mi], bl[nb][s], bl[nb][s + 2]);
                }
#pragma unroll
            for (int mi = 0; mi < 2; mi++)
#pragma unroll
                for (int nj = 0; nj < 6; nj++) {
                    const int nb = nj >> 1, s = nj & 1;
                    mma16816(acc[mi][nj], al[mi], bh[nb][s], bh[nb][s + 2]);
                }
        }
        __syncthreads();
        stage ^= 1;
    }

    // write partials
    float* pp = g_pp[kq];
#pragma unroll
    for (int mi = 0; mi < 2; mi++)
#pragma unroll
        for (int nj = 0; nj < 6; nj++) {
            int r = bm0 + wm * 32 + mi * 16 + (lane >> 2);
            int cidx = wn * 48 + nj * 8 + 2 * (lane & 3);
            *(float2*)&pp[r * IND + cidx] =
                make_float2(acc[mi][nj][0], acc[mi][nj][1]);
            *(float2*)&pp[(r + 8) * IND + cidx] =
                make_float2(acc[mi][nj][2], acc[mi][nj][3]);
        }
}

// ---------------------------------------------------------------------------
// step_predred: sum split-K partials, add bias, write output + feedback x.
// ---------------------------------------------------------------------------
__global__ __launch_bounds__(256) void step_predred(int p, int step,
                                                    float* __restrict__ out,
                                                    const float* __restrict__ b_d) {
    int idx = blockIdx.x * 256 + threadIdx.x;   // 2048*96 total
    int b = idx / IND, n = idx % IND;
    float v = g_pp[0][idx] + g_pp[1][idx] + g_pp[2][idx] + g_pp[3][idx] + b_d[n];
    out[(b * STEPS + step) * IND + n] = v;
    __half hi = __float2half_rn(v);
    g_Ahi[p ^ 1][(size_t)b * KPAD + n] = hi;
    g_Alo[p ^ 1][(size_t)b * KPAD + n] = __float2half_rn(v - __half2float(hi));
}

// ---------------------------------------------------------------------------
// Inputs: inputs, W_ih, W_hh, b_ih, b_hh, W_d, b_d
// ---------------------------------------------------------------------------
extern "C" void kernel_launch(void* const* d_in, const int* in_sizes, int n_in,
                              void* d_out, int out_size) {
    const float* inputs = (const float*)d_in[0];
    const float* W_ih   = (const float*)d_in[1];
    const float* W_hh   = (const float*)d_in[2];
    const float* b_ih   = (const float*)d_in[3];
    const float* b_hh   = (const float*)d_in[4];
    const float* W_d    = (const float*)d_in[5];
    const float* b_d    = (const float*)d_in[6];
    float* out = (float*)d_out;

    cudaFuncSetAttribute(step_gates, cudaFuncAttributeMaxDynamicSharedMemorySize, GATES_SMEM);
    cudaFuncSetAttribute(step_predpart, cudaFuncAttributeMaxDynamicSharedMemorySize, PRED_SMEM);

    prep_w<<<(GATES * KPAD + 255) / 256, 256>>>(W_ih, W_hh, b_ih, b_hh, W_d);
    prep_s<<<(BATCH * KPAD + 255) / 256, 256>>>(inputs);

    dim3 gg(MTILES, NTILES);   // 16 x 24 = 384 CTAs
    dim3 gp(MTILES, 4);        // 16 x 4  = 64 CTAs
    for (int s = 0; s < STEPS; s++) {
        int p = s & 1;
        step_gates<<<gg, 256, GATES_SMEM>>>(p);
        step_predpart<<<gp, 256, PRED_SMEM>>>(p);
        step_predred<<<(BATCH * IND) / 256, 256>>>(p, s, out, b_d);
    }
}

// round 7
// speedup vs baseline: 3.8330x; 1.2746x over previous
#include <cuda_runtime.h>
#include <cuda_fp16.h>
#include <cstdint>
#include <math.h>

#define BATCH 2048
#define UNITS 768
#define IND   96
#define KTOT  864
#define KPAD  896          /* padded to 14 x 64 */
#define GATES 3072
#define STEPS 64
#define TIN   24
#define NCH   14           /* K chunks of 64 halves */

#define MT 128
#define NTILE 128          /* 32 units x 4 gates (reorder r' = u*4+q) */
#define MTILES 16
#define NTILES 24

/* gates smem: 3 stages x 48KB (AH,BH,BL tiles of 16KB each) + bias */
#define STG_STRIDE 49152
#define T_AH 0
#define T_BH 16384
#define T_BL 32768
#define OFF_BIAS 147456
#define GATES_SMEM (OFF_BIAS + 512)     /* 147968 */

/* pred smem: 2 stages x 56KB */
#define PSTG 57344
#define P_AH 0
#define P_AL 16384
#define P_BH 32768
#define P_BL 45056
#define PRED_SMEM (2 * PSTG)            /* 114688 */

// ---------------------------------------------------------------------------
// Device globals
// ---------------------------------------------------------------------------
__device__ __half g_Ahi[2][BATCH * KPAD];   // ping-pong [x(96)|h(768)|pad] hi
__device__ __half g_Alo[2][BATCH * KPAD];   // lo (used by pred path)
__device__ float  g_c[BATCH * UNITS];       // cell state
__device__ __half g_Whi[GATES * KPAD];      // reordered [Wih|Whh|pad] hi
__device__ __half g_Wlo[GATES * KPAD];      // lo
__device__ __half g_Pdh[IND * UNITS];       // W_d hi (row n, col k)
__device__ __half g_Pdl[IND * UNITS];       // W_d lo
__device__ float  g_bsumr[GATES];           // reordered b_ih + b_hh
__device__ float  g_pp[4][BATCH * IND];     // pred split-K partials

__device__ __forceinline__ uint32_t smem_u32(const void* p) {
    uint32_t a;
    asm("{ .reg .u64 t; cvta.to.shared.u64 t, %1; cvt.u32.u64 %0, t; }" : "=r"(a) : "l"(p));
    return a;
}
__device__ __forceinline__ void cp16(uint32_t dst, const void* src) {
    asm volatile("cp.async.cg.shared.global [%0], [%1], 16;" :: "r"(dst), "l"(src));
}
__device__ __forceinline__ void ldsm4(uint32_t* r, uint32_t addr) {
    asm volatile("ldmatrix.sync.aligned.m8n8.x4.shared.b16 {%0,%1,%2,%3}, [%4];"
        : "=r"(r[0]), "=r"(r[1]), "=r"(r[2]), "=r"(r[3]) : "r"(addr));
}
__device__ __forceinline__ void mma16816(float* c, const uint32_t* a, uint32_t b0, uint32_t b1) {
    asm volatile("mma.sync.aligned.m16n8k16.row.col.f32.f16.f16.f32 "
        "{%0,%1,%2,%3}, {%4,%5,%6,%7}, {%8,%9}, {%0,%1,%2,%3};"
        : "+f"(c[0]), "+f"(c[1]), "+f"(c[2]), "+f"(c[3])
        : "r"(a[0]), "r"(a[1]), "r"(a[2]), "r"(a[3]), "r"(b0), "r"(b1));
}
// fp16-accumulate variant
__device__ __forceinline__ void mma16816h(uint32_t* c, const uint32_t* a, uint32_t b0, uint32_t b1) {
    asm volatile("mma.sync.aligned.m16n8k16.row.col.f16.f16.f16.f16 "
        "{%0,%1}, {%2,%3,%4,%5}, {%6,%7}, {%0,%1};"
        : "+r"(c[0]), "+r"(c[1])
        : "r"(a[0]), "r"(a[1]), "r"(a[2]), "r"(a[3]), "r"(b0), "r"(b1));
}
__device__ __forceinline__ float sigm(float x) { return 1.0f / (1.0f + expf(-x)); }

// ---------------------------------------------------------------------------
// prep: reordered + fp16-split weights. r' = u*4 + q  <->  orig q*768 + u.
// ---------------------------------------------------------------------------
__global__ void prep_w(const float* __restrict__ W_ih, const float* __restrict__ W_hh,
                       const float* __restrict__ b_ih, const float* __restrict__ b_hh,
                       const float* __restrict__ W_d) {
    int i = blockIdx.x * blockDim.x + threadIdx.x;
    if (i < GATES * KPAD) {
        int rp = i / KPAD, k = i % KPAD;
        int u = rp >> 2, q = rp & 3;
        int orig = q * UNITS + u;
        float w = 0.0f;
        if (k < IND)       w = W_ih[orig * IND + k];
        else if (k < KTOT) w = W_hh[orig * UNITS + (k - IND)];
        __half hi = __float2half_rn(w);
        g_Whi[i] = hi;
        g_Wlo[i] = __float2half_rn(w - __half2float(hi));
    }
    if (i < GATES) {
        int u = i >> 2, q = i & 3;
        g_bsumr[i] = b_ih[q * UNITS + u] + b_hh[q * UNITS + u];
    }
    if (i < IND * UNITS) {
        float w = W_d[i];
        __half hi = __float2half_rn(w);
        g_Pdh[i] = hi;
        g_Pdl[i] = __float2half_rn(w - __half2float(hi));
    }
}

__global__ void prep_s(const float* __restrict__ inputs) {
    int i = blockIdx.x * blockDim.x + threadIdx.x;
    if (i < BATCH * KPAD) {
        int b = i / KPAD, k = i % KPAD;
        float v = (k < IND) ? inputs[(b * TIN + (TIN - 1)) * IND + k] : 0.0f;
        __half hi = __float2half_rn(v);
        g_Ahi[0][i] = hi;
        g_Alo[0][i] = __float2half_rn(v - __half2float(hi));
        g_Ahi[1][i] = __float2half_rn(0.0f);   // pad region must stay zero
        g_Alo[1][i] = __float2half_rn(0.0f);
    }
    if (i < BATCH * UNITS) g_c[i] = 0.0f;
}

// ---------------------------------------------------------------------------
// step_gates: 2-pass fp16-split mma.sync GEMM M=128,N=128,K=896 + fused cell.
// pass hh: ah x bh, f32 accumulate (weights hi x activations fp16)
// pass hl: ah x bl, f16 accumulate (weight lo correction)
// (al x bh dropped: activations at fp16 precision; weights at 22-bit.)
// ---------------------------------------------------------------------------
__device__ __forceinline__ void load_stage(uint32_t sb, int stage, int kc, int tid,
                                           int bm0, int n0r,
                                           const __half* __restrict__ Ah) {
    uint32_t base = sb + stage * STG_STRIDE;
    int k0 = kc * 64;   // halves
#pragma unroll
    for (int i = 0; i < 4; i++) {
        int e = tid + i * 256;
        int row = e >> 3, sub = e & 7;
        uint32_t off = row * 128 + sub * 16;
        uint32_t sw = off ^ ((off >> 3) & 0x70);
        size_t gA = (size_t)(bm0 + row) * KPAD + k0 + sub * 8;
        cp16(base + T_AH + sw, Ah + gA);
        size_t gB = (size_t)(n0r + row) * KPAD + k0 + sub * 8;
        cp16(base + T_BH + sw, g_Whi + gB);
        cp16(base + T_BL + sw, g_Wlo + gB);
    }
    asm volatile("cp.async.commit_group;");
}

__global__ __launch_bounds__(256, 1) void step_gates(int p) {
    extern __shared__ __align__(1024) char smem[];
    const uint32_t sb = smem_u32(smem);
    float* sB = (float*)(smem + OFF_BIAS);
    const int tid = threadIdx.x;
    const int wid = tid >> 5;
    const int lane = tid & 31;
    const int bm0 = blockIdx.x * MT;
    const int nt  = blockIdx.y;
    const int n0r = nt * NTILE;

    const __half* __restrict__ Ah = g_Ahi[p];

    if (tid < NTILE) sB[tid] = g_bsumr[n0r + tid];

    // warp tiling: 2 (m) x 4 (n); warp tile 64 x 32
    const int wm = wid & 1, wn = wid >> 1;

    const int ra = lane & 7, qa = lane >> 3;
    const int colsel = (qa >> 1) * 16;
    int arow[4], axor[4], browr[2], bxor[2];
#pragma unroll
    for (int mi = 0; mi < 4; mi++) {
        int r = wm * 64 + mi * 16 + ra + (qa & 1) * 8;
        arow[mi] = r * 128;
        axor[mi] = (r & 7) << 4;
    }
#pragma unroll
    for (int nb = 0; nb < 2; nb++) {
        int r = wn * 32 + nb * 16 + ra + (qa & 1) * 8;
        browr[nb] = r * 128;
        bxor[nb] = (r & 7) << 4;
    }

    float acc[4][4][4];
    uint32_t acc16[4][4][2];   // f16 accumulators for weight-lo correction
#pragma unroll
    for (int mi = 0; mi < 4; mi++)
#pragma unroll
        for (int ni = 0; ni < 4; ni++) {
#pragma unroll
            for (int j = 0; j < 4; j++) acc[mi][ni][j] = 0.0f;
            acc16[mi][ni][0] = 0u;
            acc16[mi][ni][1] = 0u;
        }

    load_stage(sb, 0, 0, tid, bm0, n0r, Ah);
    load_stage(sb, 1, 1, tid, bm0, n0r, Ah);

#pragma unroll 1
    for (int i = 0; i < NCH; i++) {
        if (i + 2 < NCH) {
            load_stage(sb, (i + 2) % 3, i + 2, tid, bm0, n0r, Ah);
            asm volatile("cp.async.wait_group 2;");
        } else if (i + 1 < NCH) {
            asm volatile("cp.async.wait_group 1;");
        } else {
            asm volatile("cp.async.wait_group 0;");
        }
        __syncthreads();

        uint32_t base = sb + (i % 3) * STG_STRIDE;
#pragma unroll
        for (int kk = 0; kk < 4; kk++) {
            const int colb = kk * 32 + colsel;
            uint32_t ah[4][4], bh[2][4], bl[2][4];
#pragma unroll
            for (int mi = 0; mi < 4; mi++)
                ldsm4(ah[mi], base + T_AH + arow[mi] + (colb ^ axor[mi]));
#pragma unroll
            for (int nb = 0; nb < 2; nb++) {
                ldsm4(bh[nb], base + T_BH + browr[nb] + (colb ^ bxor[nb]));
                ldsm4(bl[nb], base + T_BL + browr[nb] + (colb ^ bxor[nb]));
            }
            // pass hh: f32 accumulate (16 independent accumulators)
#pragma unroll
            for (int mi = 0; mi < 4; mi++)
#pragma unroll
                for (int ni = 0; ni < 4; ni++) {
                    const int nb = ni >> 1, s = ni & 1;
                    mma16816(acc[mi][ni], ah[mi], bh[nb][s], bh[nb][s + 2]);
                }
            // pass hl: f16 accumulate
#pragma unroll
            for (int mi = 0; mi < 4; mi++)
#pragma unroll
                for (int ni = 0; ni < 4; ni++) {
                    const int nb = ni >> 1, s = ni & 1;
                    mma16816h(acc16[mi][ni], ah[mi], bl[nb][s], bl[nb][s + 2]);
                }
        }
        __syncthreads();
    }

    // fold f16 correction accumulators into f32 accumulators
#pragma unroll
    for (int mi = 0; mi < 4; mi++)
#pragma unroll
        for (int ni = 0; ni < 4; ni++) {
            float2 c0 = __half22float2(*(__half2*)&acc16[mi][ni][0]);
            float2 c1 = __half22float2(*(__half2*)&acc16[mi][ni][1]);
            acc[mi][ni][0] += c0.x;
            acc[mi][ni][1] += c0.y;
            acc[mi][ni][2] += c1.x;
            acc[mi][ni][3] += c1.y;
        }

    // ---- epilogue: frags -> smem, fused LSTM cell ----
    float* sC = (float*)smem;   // [128][132]
#pragma unroll
    for (int mi = 0; mi < 4; mi++)
#pragma unroll
        for (int ni = 0; ni < 4; ni++) {
            int r = wm * 64 + mi * 16 + (lane >> 2);
            int cidx = wn * 32 + ni * 8 + 2 * (lane & 3);
            sC[r * 132 + cidx]           = acc[mi][ni][0];
            sC[r * 132 + cidx + 1]       = acc[mi][ni][1];
            sC[(r + 8) * 132 + cidx]     = acc[mi][ni][2];
            sC[(r + 8) * 132 + cidx + 1] = acc[mi][ni][3];
        }
    __syncthreads();

    __half* __restrict__ nAh = g_Ahi[p ^ 1];
    __half* __restrict__ nAl = g_Alo[p ^ 1];
#pragma unroll
    for (int it = 0; it < 16; it++) {
        int idx = tid + it * 256;
        int row = idx >> 5, ul = idx & 31;
        int m = bm0 + row, ug = nt * 32 + ul;
        float iv = sigm(sC[row * 132 + ul * 4 + 0] + sB[ul * 4 + 0]);
        float fv = sigm(sC[row * 132 + ul * 4 + 1] + sB[ul * 4 + 1]);
        float gv = tanhf(sC[row * 132 + ul * 4 + 2] + sB[ul * 4 + 2]);
        float ov = sigm(sC[row * 132 + ul * 4 + 3] + sB[ul * 4 + 3]);
        float cv = fv * g_c[m * UNITS + ug] + iv * gv;
        g_c[m * UNITS + ug] = cv;
        float hv = ov * tanhf(cv);
        __half hi = __float2half_rn(hv);
        nAh[(size_t)m * KPAD + IND + ug] = hi;
        nAl[(size_t)m * KPAD + IND + ug] = __float2half_rn(hv - __half2float(hi));
    }
}

// ---------------------------------------------------------------------------
// step_predpart: split-K tensor GEMM (full 3-pass split for accuracy).
// Grid (16 M-tiles, 4 K-slices). CTA: M=128, N=96, K=192 (3 chunks of 64).
// ---------------------------------------------------------------------------
__device__ __forceinline__ void load_pstage(uint32_t sb, int stage, int kq, int c,
                                            int tid, int bm0,
                                            const __half* __restrict__ Ah,
                                            const __half* __restrict__ Al) {
    uint32_t base = sb + stage * PSTG;
    int k0 = kq * 192 + c * 64;
#pragma unroll
    for (int i = 0; i < 4; i++) {      // A: 128 rows
        int e = tid + i * 256;
        int row = e >> 3, sub = e & 7;
        uint32_t off = row * 128 + sub * 16;
        uint32_t sw = off ^ ((off >> 3) & 0x70);
        size_t gA = (size_t)(bm0 + row) * KPAD + IND + k0 + sub * 8;
        cp16(base + P_AH + sw, Ah + gA);
        cp16(base + P_AL + sw, Al + gA);
    }
#pragma unroll
    for (int i = 0; i < 3; i++) {      // B: 96 rows
        int e = tid + i * 256;
        int row = e >> 3, sub = e & 7;
        uint32_t off = row * 128 + sub * 16;
        uint32_t sw = off ^ ((off >> 3) & 0x70);
        size_t gB = (size_t)row * UNITS + k0 + sub * 8;
        cp16(base + P_BH + sw, g_Pdh + gB);
        cp16(base + P_BL + sw, g_Pdl + gB);
    }
    asm volatile("cp.async.commit_group;");
}

__global__ __launch_bounds__(256, 1) void step_predpart(int p) {
    extern __shared__ __align__(1024) char smem[];
    const uint32_t sb = smem_u32(smem);
    const int tid = threadIdx.x;
    const int wid = tid >> 5;
    const int lane = tid & 31;
    const int bm0 = blockIdx.x * MT;
    const int kq  = blockIdx.y;

    const __half* __restrict__ Ah = g_Ahi[p ^ 1];
    const __half* __restrict__ Al = g_Alo[p ^ 1];

    // warp tiling: 4 (m) x 2 (n); warp tile 32 x 48
    const int wm = wid & 3, wn = wid >> 2;

    const int ra = lane & 7, qa = lane >> 3;
    const int colsel = (qa >> 1) * 16;
    int arow[2], axor[2], browr[3], bxor[3];
#pragma unroll
    for (int mi = 0; mi < 2; mi++) {
        int r = wm * 32 + mi * 16 + ra + (qa & 1) * 8;
        arow[mi] = r * 128;
        axor[mi] = (r & 7) << 4;
    }
#pragma unroll
    for (int nb = 0; nb < 3; nb++) {
        int r = wn * 48 + nb * 16 + ra + (qa & 1) * 8;
        browr[nb] = r * 128;
        bxor[nb] = (r & 7) << 4;
    }

    float acc[2][6][4];
#pragma unroll
    for (int mi = 0; mi < 2; mi++)
#pragma unroll
        for (int nj = 0; nj < 6; nj++)
#pragma unroll
            for (int j = 0; j < 4; j++) acc[mi][nj][j] = 0.0f;

    load_pstage(sb, 0, kq, 0, tid, bm0, Ah, Al);

    int stage = 0;
#pragma unroll 1
    for (int c = 0; c < 3; c++) {
        if (c + 1 < 3) {
            load_pstage(sb, stage ^ 1, kq, c + 1, tid, bm0, Ah, Al);
            asm volatile("cp.async.wait_group 1;");
        } else {
            asm volatile("cp.async.wait_group 0;");
        }
        __syncthreads();

        uint32_t base = sb + stage * PSTG;
#pragma unroll
        for (int kk = 0; kk < 4; kk++) {
            const int colb = kk * 32 + colsel;
            uint32_t ah[2][4], al[2][4], bh[3][4], bl[3][4];
#pragma unroll
            for (int mi = 0; mi < 2; mi++) {
                ldsm4(ah[mi], base + P_AH + arow[mi] + (colb ^ axor[mi]));
                ldsm4(al[mi], base + P_AL + arow[mi] + (colb ^ axor[mi]));
            }
#pragma unroll
            for (int nb = 0; nb < 3; nb++) {
                ldsm4(bh[nb], base + P_BH + browr[nb] + (colb ^ bxor[nb]));
                ldsm4(bl[nb], base + P_BL + browr[nb] + (colb ^ bxor[nb]));
            }
#pragma unroll
            for (int mi = 0; mi < 2; mi++)
#pragma unroll
                for (int nj = 0; nj < 6; nj++) {
                    const int nb = nj >> 1, s = nj & 1;
                    mma16816(acc[mi][nj], ah[mi], bh[nb][s], bh[nb][s + 2]);
                }
#pragma unroll
            for (int mi = 0; mi < 2; mi++)
#pragma unroll
                for (int nj = 0; nj < 6; nj++) {
                    const int nb = nj >> 1, s = nj & 1;
                    mma16816(acc[mi][nj], ah[mi], bl[nb][s], bl[nb][s + 2]);
                }
#pragma unroll
            for (int mi = 0; mi < 2; mi++)
#pragma unroll
                for (int nj = 0; nj < 6; nj++) {
                    const int nb = nj >> 1, s = nj & 1;
                    mma16816(acc[mi][nj], al[mi], bh[nb][s], bh[nb][s + 2]);
                }
        }
        __syncthreads();
        stage ^= 1;
    }

    // write partials
    float* pp = g_pp[kq];
#pragma unroll
    for (int mi = 0; mi < 2; mi++)
#pragma unroll
        for (int nj = 0; nj < 6; nj++) {
            int r = bm0 + wm * 32 + mi * 16 + (lane >> 2);
            int cidx = wn * 48 + nj * 8 + 2 * (lane & 3);
            *(float2*)&pp[r * IND + cidx] =
                make_float2(acc[mi][nj][0], acc[mi][nj][1]);
            *(float2*)&pp[(r + 8) * IND + cidx] =
                make_float2(acc[mi][nj][2], acc[mi][nj][3]);
        }
}

// ---------------------------------------------------------------------------
// step_predred: sum split-K partials, add bias, write output + feedback x.
// ---------------------------------------------------------------------------
__global__ __launch_bounds__(256) void step_predred(int p, int step,
                                                    float* __restrict__ out,
                                                    const float* __restrict__ b_d) {
    int idx = blockIdx.x * 256 + threadIdx.x;   // 2048*96 total
    int b = idx / IND, n = idx % IND;
    float v = g_pp[0][idx] + g_pp[1][idx] + g_pp[2][idx] + g_pp[3][idx] + b_d[n];
    out[(b * STEPS + step) * IND + n] = v;
    __half hi = __float2half_rn(v);
    g_Ahi[p ^ 1][(size_t)b * KPAD + n] = hi;
    g_Alo[p ^ 1][(size_t)b * KPAD + n] = __float2half_rn(v - __half2float(hi));
}

// ---------------------------------------------------------------------------
// Inputs: inputs, W_ih, W_hh, b_ih, b_hh, W_d, b_d
// ---------------------------------------------------------------------------
extern "C" void kernel_launch(void* const* d_in, const int* in_sizes, int n_in,
                              void* d_out, int out_size) {
    const float* inputs = (const float*)d_in[0];
    const float* W_ih   = (const float*)d_in[1];
    const float* W_hh   = (const float*)d_in[2];
    const float* b_ih   = (const float*)d_in[3];
    const float* b_hh   = (const float*)d_in[4];
    const float* W_d    = (const float*)d_in[5];
    const float* b_d    = (const float*)d_in[6];
    float* out = (float*)d_out;

    cudaFuncSetAttribute(step_gates, cudaFuncAttributeMaxDynamicSharedMemorySize, GATES_SMEM);
    cudaFuncSetAttribute(step_predpart, cudaFuncAttributeMaxDynamicSharedMemorySize, PRED_SMEM);

    prep_w<<<(GATES * KPAD + 255) / 256, 256>>>(W_ih, W_hh, b_ih, b_hh, W_d);
    prep_s<<<(BATCH * KPAD + 255) / 256, 256>>>(inputs);

    dim3 gg(MTILES, NTILES);   // 16 x 24 = 384 CTAs
    dim3 gp(MTILES, 4);        // 16 x 4  = 64 CTAs
    for (int s = 0; s < STEPS; s++) {
        int p = s & 1;
        step_gates<<<gg, 256, GATES_SMEM>>>(p);
        step_predpart<<<gp, 256, PRED_SMEM>>>(p);
        step_predred<<<(BATCH * IND) / 256, 256>>>(p, s, out, b_d);
    }
}

// round 8
// speedup vs baseline: 6.2969x; 1.6428x over previous
#include <cuda_runtime.h>
#include <cuda_fp16.h>
#include <cstdint>
#include <math.h>

#define BATCH 2048
#define UNITS 768
#define IND   96
#define KTOT  864
#define KPAD  896          /* padded to 14 x 64 */
#define GATES 3072
#define STEPS 64
#define TIN   24
#define NCH   14           /* K chunks of 64 halves */

#define MT 128
#define NTILE 128          /* 32 units x 4 gates (reorder r' = u*4+q) */
#define MTILES 16
#define NTILES 24

/* gates smem: 3 stages x 32KB (AH,BH tiles of 16KB each) + bias */
#define STG_STRIDE 32768
#define T_AH 0
#define T_BH 16384
#define OFF_BIAS 98304
#define GATES_SMEM (OFF_BIAS + 512)     /* 98816 -> 2 CTAs/SM */

/* pred smem: 2 stages x 56KB */
#define PSTG 57344
#define P_AH 0
#define P_AL 16384
#define P_BH 32768
#define P_BL 45056
#define PRED_SMEM (2 * PSTG)            /* 114688 */

// ---------------------------------------------------------------------------
// Device globals
// ---------------------------------------------------------------------------
__device__ __half g_Ahi[2][BATCH * KPAD];   // ping-pong [x(96)|h(768)|pad] hi
__device__ __half g_Alo[2][BATCH * KPAD];   // lo (pred path only)
__device__ float  g_c[BATCH * UNITS];       // cell state
__device__ __half g_Whi[GATES * KPAD];      // reordered [Wih|Whh|pad] fp16
__device__ __half g_Pdh[IND * UNITS];       // W_d hi (row n, col k)
__device__ __half g_Pdl[IND * UNITS];       // W_d lo
__device__ float  g_bsumr[GATES];           // reordered b_ih + b_hh
__device__ float  g_pp[4][BATCH * IND];     // pred split-K partials

__device__ __forceinline__ uint32_t smem_u32(const void* p) {
    uint32_t a;
    asm("{ .reg .u64 t; cvta.to.shared.u64 t, %1; cvt.u32.u64 %0, t; }" : "=r"(a) : "l"(p));
    return a;
}
__device__ __forceinline__ void cp16(uint32_t dst, const void* src) {
    asm volatile("cp.async.cg.shared.global [%0], [%1], 16;" :: "r"(dst), "l"(src));
}
__device__ __forceinline__ void ldsm4(uint32_t* r, uint32_t addr) {
    asm volatile("ldmatrix.sync.aligned.m8n8.x4.shared.b16 {%0,%1,%2,%3}, [%4];"
        : "=r"(r[0]), "=r"(r[1]), "=r"(r[2]), "=r"(r[3]) : "r"(addr));
}
__device__ __forceinline__ void mma16816(float* c, const uint32_t* a, uint32_t b0, uint32_t b1) {
    asm volatile("mma.sync.aligned.m16n8k16.row.col.f32.f16.f16.f32 "
        "{%0,%1,%2,%3}, {%4,%5,%6,%7}, {%8,%9}, {%0,%1,%2,%3};"
        : "+f"(c[0]), "+f"(c[1]), "+f"(c[2]), "+f"(c[3])
        : "r"(a[0]), "r"(a[1]), "r"(a[2]), "r"(a[3]), "r"(b0), "r"(b1));
}
__device__ __forceinline__ float sigm(float x) { return 1.0f / (1.0f + expf(-x)); }

// ---------------------------------------------------------------------------
// prep: reordered fp16 weights. r' = u*4 + q  <->  orig q*768 + u.
// ---------------------------------------------------------------------------
__global__ void prep_w(const float* __restrict__ W_ih, const float* __restrict__ W_hh,
                       const float* __restrict__ b_ih, const float* __restrict__ b_hh,
                       const float* __restrict__ W_d) {
    int i = blockIdx.x * blockDim.x + threadIdx.x;
    if (i < GATES * KPAD) {
        int rp = i / KPAD, k = i % KPAD;
        int u = rp >> 2, q = rp & 3;
        int orig = q * UNITS + u;
        float w = 0.0f;
        if (k < IND)       w = W_ih[orig * IND + k];
        else if (k < KTOT) w = W_hh[orig * UNITS + (k - IND)];
        g_Whi[i] = __float2half_rn(w);
    }
    if (i < GATES) {
        int u = i >> 2, q = i & 3;
        g_bsumr[i] = b_ih[q * UNITS + u] + b_hh[q * UNITS + u];
    }
    if (i < IND * UNITS) {
        float w = W_d[i];
        __half hi = __float2half_rn(w);
        g_Pdh[i] = hi;
        g_Pdl[i] = __float2half_rn(w - __half2float(hi));
    }
}

__global__ void prep_s(const float* __restrict__ inputs) {
    int i = blockIdx.x * blockDim.x + threadIdx.x;
    if (i < BATCH * KPAD) {
        int b = i / KPAD, k = i % KPAD;
        float v = (k < IND) ? inputs[(b * TIN + (TIN - 1)) * IND + k] : 0.0f;
        __half hi = __float2half_rn(v);
        g_Ahi[0][i] = hi;
        g_Alo[0][i] = __float2half_rn(v - __half2float(hi));
        g_Ahi[1][i] = __float2half_rn(0.0f);   // pad region must stay zero
        g_Alo[1][i] = __float2half_rn(0.0f);
    }
    if (i < BATCH * UNITS) g_c[i] = 0.0f;
}

// ---------------------------------------------------------------------------
// step_gates: single-pass fp16 mma.sync GEMM M=128,N=128,K=896 (f32 acc)
//             + fused LSTM cell epilogue.
// ---------------------------------------------------------------------------
__device__ __forceinline__ void load_stage(uint32_t sb, int stage, int kc, int tid,
                                           int bm0, int n0r,
                                           const __half* __restrict__ Ah) {
    uint32_t base = sb + stage * STG_STRIDE;
    int k0 = kc * 64;   // halves
#pragma unroll
    for (int i = 0; i < 4; i++) {
        int e = tid + i * 256;
        int row = e >> 3, sub = e & 7;
        uint32_t off = row * 128 + sub * 16;
        uint32_t sw = off ^ ((off >> 3) & 0x70);
        size_t gA = (size_t)(bm0 + row) * KPAD + k0 + sub * 8;
        cp16(base + T_AH + sw, Ah + gA);
        size_t gB = (size_t)(n0r + row) * KPAD + k0 + sub * 8;
        cp16(base + T_BH + sw, g_Whi + gB);
    }
    asm volatile("cp.async.commit_group;");
}

__global__ __launch_bounds__(256) void step_gates(int p) {
    extern __shared__ __align__(1024) char smem[];
    const uint32_t sb = smem_u32(smem);
    float* sB = (float*)(smem + OFF_BIAS);
    const int tid = threadIdx.x;
    const int wid = tid >> 5;
    const int lane = tid & 31;
    const int bm0 = blockIdx.x * MT;
    const int nt  = blockIdx.y;
    const int n0r = nt * NTILE;

    const __half* __restrict__ Ah = g_Ahi[p];

    if (tid < NTILE) sB[tid] = g_bsumr[n0r + tid];

    // warp tiling: 2 (m) x 4 (n); warp tile 64 x 32
    const int wm = wid & 1, wn = wid >> 1;

    const int ra = lane & 7, qa = lane >> 3;
    const int colsel = (qa >> 1) * 16;
    int arow[4], axor[4], browr[2], bxor[2];
#pragma unroll
    for (int mi = 0; mi < 4; mi++) {
        int r = wm * 64 + mi * 16 + ra + (qa & 1) * 8;
        arow[mi] = r * 128;
        axor[mi] = (r & 7) << 4;
    }
#pragma unroll
    for (int nb = 0; nb < 2; nb++) {
        int r = wn * 32 + nb * 16 + ra + (qa & 1) * 8;
        browr[nb] = r * 128;
        bxor[nb] = (r & 7) << 4;
    }

    float acc[4][4][4];
#pragma unroll
    for (int mi = 0; mi < 4; mi++)
#pragma unroll
        for (int ni = 0; ni < 4; ni++)
#pragma unroll
            for (int j = 0; j < 4; j++) acc[mi][ni][j] = 0.0f;

    load_stage(sb, 0, 0, tid, bm0, n0r, Ah);
    load_stage(sb, 1, 1, tid, bm0, n0r, Ah);

#pragma unroll 1
    for (int i = 0; i < NCH; i++) {
        if (i + 2 < NCH) {
            load_stage(sb, (i + 2) % 3, i + 2, tid, bm0, n0r, Ah);
            asm volatile("cp.async.wait_group 2;");
        } else if (i + 1 < NCH) {
            asm volatile("cp.async.wait_group 1;");
        } else {
            asm volatile("cp.async.wait_group 0;");
        }
        __syncthreads();

        uint32_t base = sb + (i % 3) * STG_STRIDE;
#pragma unroll
        for (int kk = 0; kk < 4; kk++) {
            const int colb = kk * 32 + colsel;
            uint32_t ah[4][4], bh[2][4];
#pragma unroll
            for (int mi = 0; mi < 4; mi++)
                ldsm4(ah[mi], base + T_AH + arow[mi] + (colb ^ axor[mi]));
#pragma unroll
            for (int nb = 0; nb < 2; nb++)
                ldsm4(bh[nb], base + T_BH + browr[nb] + (colb ^ bxor[nb]));
#pragma unroll
            for (int mi = 0; mi < 4; mi++)
#pragma unroll
                for (int ni = 0; ni < 4; ni++) {
                    const int nb = ni >> 1, s = ni & 1;
                    mma16816(acc[mi][ni], ah[mi], bh[nb][s], bh[nb][s + 2]);
                }
        }
        __syncthreads();
    }

    // ---- epilogue: frags -> smem, fused LSTM cell ----
    float* sC = (float*)smem;   // [128][132] = 67584 B < 98304
#pragma unroll
    for (int mi = 0; mi < 4; mi++)
#pragma unroll
        for (int ni = 0; ni < 4; ni++) {
            int r = wm * 64 + mi * 16 + (lane >> 2);
            int cidx = wn * 32 + ni * 8 + 2 * (lane & 3);
            sC[r * 132 + cidx]           = acc[mi][ni][0];
            sC[r * 132 + cidx + 1]       = acc[mi][ni][1];
            sC[(r + 8) * 132 + cidx]     = acc[mi][ni][2];
            sC[(r + 8) * 132 + cidx + 1] = acc[mi][ni][3];
        }
    __syncthreads();

    __half* __restrict__ nAh = g_Ahi[p ^ 1];
    __half* __restrict__ nAl = g_Alo[p ^ 1];
#pragma unroll
    for (int it = 0; it < 16; it++) {
        int idx = tid + it * 256;
        int row = idx >> 5, ul = idx & 31;
        int m = bm0 + row, ug = nt * 32 + ul;
        float iv = sigm(sC[row * 132 + ul * 4 + 0] + sB[ul * 4 + 0]);
        float fv = sigm(sC[row * 132 + ul * 4 + 1] + sB[ul * 4 + 1]);
        float gv = tanhf(sC[row * 132 + ul * 4 + 2] + sB[ul * 4 + 2]);
        float ov = sigm(sC[row * 132 + ul * 4 + 3] + sB[ul * 4 + 3]);
        float cv = fv * g_c[m * UNITS + ug] + iv * gv;
        g_c[m * UNITS + ug] = cv;
        float hv = ov * tanhf(cv);
        __half hi = __float2half_rn(hv);
        nAh[(size_t)m * KPAD + IND + ug] = hi;
        nAl[(size_t)m * KPAD + IND + ug] = __float2half_rn(hv - __half2float(hi));
    }
}

// ---------------------------------------------------------------------------
// step_predpart: split-K tensor GEMM (full 3-pass split for accuracy).
// Grid (16 M-tiles, 4 K-slices). CTA: M=128, N=96, K=192 (3 chunks of 64).
// ---------------------------------------------------------------------------
__device__ __forceinline__ void load_pstage(uint32_t sb, int stage, int kq, int c,
                                            int tid, int bm0,
                                            const __half* __restrict__ Ah,
                                            const __half* __restrict__ Al) {
    uint32_t base = sb + stage * PSTG;
    int k0 = kq * 192 + c * 64;
#pragma unroll
    for (int i = 0; i < 4; i++) {      // A: 128 rows
        int e = tid + i * 256;
        int row = e >> 3, sub = e & 7;
        uint32_t off = row * 128 + sub * 16;
        uint32_t sw = off ^ ((off >> 3) & 0x70);
        size_t gA = (size_t)(bm0 + row) * KPAD + IND + k0 + sub * 8;
        cp16(base + P_AH + sw, Ah + gA);
        cp16(base + P_AL + sw, Al + gA);
    }
#pragma unroll
    for (int i = 0; i < 3; i++) {      // B: 96 rows
        int e = tid + i * 256;
        int row = e >> 3, sub = e & 7;
        uint32_t off = row * 128 + sub * 16;
        uint32_t sw = off ^ ((off >> 3) & 0x70);
        size_t gB = (size_t)row * UNITS + k0 + sub * 8;
        cp16(base + P_BH + sw, g_Pdh + gB);
        cp16(base + P_BL + sw, g_Pdl + gB);
    }
    asm volatile("cp.async.commit_group;");
}

__global__ __launch_bounds__(256, 1) void step_predpart(int p) {
    extern __shared__ __align__(1024) char smem[];
    const uint32_t sb = smem_u32(smem);
    const int tid = threadIdx.x;
    const int wid = tid >> 5;
    const int lane = tid & 31;
    const int bm0 = blockIdx.x * MT;
    const int kq  = blockIdx.y;

    const __half* __restrict__ Ah = g_Ahi[p ^ 1];
    const __half* __restrict__ Al = g_Alo[p ^ 1];

    // warp tiling: 4 (m) x 2 (n); warp tile 32 x 48
    const int wm = wid & 3, wn = wid >> 2;

    const int ra = lane & 7, qa = lane >> 3;
    const int colsel = (qa >> 1) * 16;
    int arow[2], axor[2], browr[3], bxor[3];
#pragma unroll
    for (int mi = 0; mi < 2; mi++) {
        int r = wm * 32 + mi * 16 + ra + (qa & 1) * 8;
        arow[mi] = r * 128;
        axor[mi] = (r & 7) << 4;
    }
#pragma unroll
    for (int nb = 0; nb < 3; nb++) {
        int r = wn * 48 + nb * 16 + ra + (qa & 1) * 8;
        browr[nb] = r * 128;
        bxor[nb] = (r & 7) << 4;
    }

    float acc[2][6][4];
#pragma unroll
    for (int mi = 0; mi < 2; mi++)
#pragma unroll
        for (int nj = 0; nj < 6; nj++)
#pragma unroll
            for (int j = 0; j < 4; j++) acc[mi][nj][j] = 0.0f;

    load_pstage(sb, 0, kq, 0, tid, bm0, Ah, Al);

    int stage = 0;
#pragma unroll 1
    for (int c = 0; c < 3; c++) {
        if (c + 1 < 3) {
            load_pstage(sb, stage ^ 1, kq, c + 1, tid, bm0, Ah, Al);
            asm volatile("cp.async.wait_group 1;");
        } else {
            asm volatile("cp.async.wait_group 0;");
        }
        __syncthreads();

        uint32_t base = sb + stage * PSTG;
#pragma unroll
        for (int kk = 0; kk < 4; kk++) {
            const int colb = kk * 32 + colsel;
            uint32_t ah[2][4], al[2][4], bh[3][4], bl[3][4];
#pragma unroll
            for (int mi = 0; mi < 2; mi++) {
                ldsm4(ah[mi], base + P_AH + arow[mi] + (colb ^ axor[mi]));
                ldsm4(al[mi], base + P_AL + arow[mi] + (colb ^ axor[mi]));
            }
#pragma unroll
            for (int nb = 0; nb < 3; nb++) {
                ldsm4(bh[nb], base + P_BH + browr[nb] + (colb ^ bxor[nb]));
                ldsm4(bl[nb], base + P_BL + browr[nb] + (colb ^ bxor[nb]));
            }
#pragma unroll
            for (int mi = 0; mi < 2; mi++)
#pragma unroll
                for (int nj = 0; nj < 6; nj++) {
                    const int nb = nj >> 1, s = nj & 1;
                    mma16816(acc[mi][nj], ah[mi], bh[nb][s], bh[nb][s + 2]);
                }
#pragma unroll
            for (int mi = 0; mi < 2; mi++)
#pragma unroll
                for (int nj = 0; nj < 6; nj++) {
                    const int nb = nj >> 1, s = nj & 1;
                    mma16816(acc[mi][nj], ah[mi], bl[nb][s], bl[nb][s + 2]);
                }
#pragma unroll
            for (int mi = 0; mi < 2; mi++)
#pragma unroll
                for (int nj = 0; nj < 6; nj++) {
                    const int nb = nj >> 1, s = nj & 1;
                    mma16816(acc[mi][nj], al[mi], bh[nb][s], bh[nb][s + 2]);
                }
        }
        __syncthreads();
        stage ^= 1;
    }

    // write partials
    float* pp = g_pp[kq];
#pragma unroll
    for (int mi = 0; mi < 2; mi++)
#pragma unroll
        for (int nj = 0; nj < 6; nj++) {
            int r = bm0 + wm * 32 + mi * 16 + (lane >> 2);
            int cidx = wn * 48 + nj * 8 + 2 * (lane & 3);
            *(float2*)&pp[r * IND + cidx] =
                make_float2(acc[mi][nj][0], acc[mi][nj][1]);
            *(float2*)&pp[(r + 8) * IND + cidx] =
                make_float2(acc[mi][nj][2], acc[mi][nj][3]);
        }
}

// ---------------------------------------------------------------------------
// step_predred: sum split-K partials, add bias, write output + feedback x.
// ---------------------------------------------------------------------------
__global__ __launch_bounds__(256) void step_predred(int p, int step,
                                                    float* __restrict__ out,
                                                    const float* __restrict__ b_d) {
    int idx = blockIdx.x * 256 + threadIdx.x;   // 2048*96 total
    int b = idx / IND, n = idx % IND;
    float v = g_pp[0][idx] + g_pp[1][idx] + g_pp[2][idx] + g_pp[3][idx] + b_d[n];
    out[(b * STEPS + step) * IND + n] = v;
    __half hi = __float2half_rn(v);
    g_Ahi[p ^ 1][(size_t)b * KPAD + n] = hi;
    g_Alo[p ^ 1][(size_t)b * KPAD + n] = __float2half_rn(v - __half2float(hi));
}

// ---------------------------------------------------------------------------
// Inputs: inputs, W_ih, W_hh, b_ih, b_hh, W_d, b_d
// ---------------------------------------------------------------------------
extern "C" void kernel_launch(void* const* d_in, const int* in_sizes, int n_in,
                              void* d_out, int out_size) {
    const float* inputs = (const float*)d_in[0];
    const float* W_ih   = (const float*)d_in[1];
    const float* W_hh   = (const float*)d_in[2];
    const float* b_ih   = (const float*)d_in[3];
    const float* b_hh   = (const float*)d_in[4];
    const float* W_d    = (const float*)d_in[5];
    const float* b_d    = (const float*)d_in[6];
    float* out = (float*)d_out;

    cudaFuncSetAttribute(step_gates, cudaFuncAttributeMaxDynamicSharedMemorySize, GATES_SMEM);
    cudaFuncSetAttribute(step_predpart, cudaFuncAttributeMaxDynamicSharedMemorySize, PRED_SMEM);

    prep_w<<<(GATES * KPAD + 255) / 256, 256>>>(W_ih, W_hh, b_ih, b_hh, W_d);
    prep_s<<<(BATCH * KPAD + 255) / 256, 256>>>(inputs);

    dim3 gg(MTILES, NTILES);   // 16 x 24 = 384 CTAs, 2 CTAs/SM
    dim3 gp(MTILES, 4);        // 16 x 4  = 64 CTAs
    for (int s = 0; s < STEPS; s++) {
        int p = s & 1;
        step_gates<<<gg, 256, GATES_SMEM>>>(p);
        step_predpart<<<gp, 256, PRED_SMEM>>>(p);
        step_predred<<<(BATCH * IND) / 256, 256>>>(p, s, out, b_d);
    }
}

// round 9
// speedup vs baseline: 8.3526x; 1.3265x over previous
#include <cuda_runtime.h>
#include <cuda_fp16.h>
#include <cstdint>
#include <math.h>

#define BATCH 2048
#define UNITS 768
#define IND   96
#define GATES 3072
#define STEPS 64
#define TIN   24

#define MT 128
#define NTILE 128          /* 32 units x 4 gates (reorder r' = u*4+q) */
#define MTILES 16
#define NTILES 24

#define KP_MAIN 768        /* steps >= 1: K = UNITS */
#define NCH_MAIN 12
#define KP0 128            /* step 0: K = IND padded to 128 */
#define NCH0 2

/* gates smem: 3 stages x 32KB (A,B tiles of 16KB each) + bias */
#define STG_STRIDE 32768
#define T_AH 0
#define T_BH 16384
#define OFF_BIAS 98304
#define GATES_SMEM (OFF_BIAS + 512)     /* 98816 -> 2 CTAs/SM */

/* pred_all smem: 2 stages x 28KB (A 16KB + B 12KB) */
#define PSTG 28672
#define P_A  0
#define P_BH 16384
#define PRED_SMEM (2 * PSTG)            /* 57344 */

// ---------------------------------------------------------------------------
// Device globals
// ---------------------------------------------------------------------------
__device__ __half g_hist[(size_t)STEPS * BATCH * UNITS];  // h history (192 MB)
__device__ __half g_x0[BATCH * KP0];        // step-0 input, padded
__device__ float  g_c[BATCH * UNITS];       // cell state
__device__ __half g_Weff[GATES * UNITS];    // reordered W_hh + W_ih@W_d (fp16)
__device__ __half g_Wih16[GATES * KP0];     // reordered W_ih (fp16, padded)
__device__ __half g_Pdh[IND * UNITS];       // W_d fp16 (row n, col k)
__device__ float  g_b0[GATES];              // reordered b_ih + b_hh
__device__ float  g_beff[GATES];            // reordered b_ih + b_hh + W_ih@b_d

__device__ __forceinline__ uint32_t smem_u32(const void* p) {
    uint32_t a;
    asm("{ .reg .u64 t; cvta.to.shared.u64 t, %1; cvt.u32.u64 %0, t; }" : "=r"(a) : "l"(p));
    return a;
}
__device__ __forceinline__ void cp16(uint32_t dst, const void* src) {
    asm volatile("cp.async.cg.shared.global [%0], [%1], 16;" :: "r"(dst), "l"(src));
}
__device__ __forceinline__ void ldsm4(uint32_t* r, uint32_t addr) {
    asm volatile("ldmatrix.sync.aligned.m8n8.x4.shared.b16 {%0,%1,%2,%3}, [%4];"
        : "=r"(r[0]), "=r"(r[1]), "=r"(r[2]), "=r"(r[3]) : "r"(addr));
}
__device__ __forceinline__ void mma16816(float* c, const uint32_t* a, uint32_t b0, uint32_t b1) {
    asm volatile("mma.sync.aligned.m16n8k16.row.col.f32.f16.f16.f32 "
        "{%0,%1,%2,%3}, {%4,%5,%6,%7}, {%8,%9}, {%0,%1,%2,%3};"
        : "+f"(c[0]), "+f"(c[1]), "+f"(c[2]), "+f"(c[3])
        : "r"(a[0]), "r"(a[1]), "r"(a[2]), "r"(a[3]), "r"(b0), "r"(b1));
}
__device__ __forceinline__ float sigm(float x) { return 1.0f / (1.0f + expf(-x)); }

// ---------------------------------------------------------------------------
// prep_w: reordered W_ih (fp16, K padded to 128), W_d fp16, biases.
// Reorder: r' = u*4 + q  <->  orig row q*768 + u.
// ---------------------------------------------------------------------------
__global__ void prep_w(const float* __restrict__ W_ih,
                       const float* __restrict__ b_ih, const float* __restrict__ b_hh,
                       const float* __restrict__ W_d, const float* __restrict__ b_d) {
    int i = blockIdx.x * blockDim.x + threadIdx.x;
    if (i < GATES * KP0) {
        int rp = i / KP0, k = i % KP0;
        int orig = (rp & 3) * UNITS + (rp >> 2);
        float w = (k < IND) ? W_ih[orig * IND + k] : 0.0f;
        g_Wih16[i] = __float2half_rn(w);
    }
    if (i < IND * UNITS) g_Pdh[i] = __float2half_rn(W_d[i]);
    if (i < GATES) {
        int orig = (i & 3) * UNITS + (i >> 2);
        float b0 = b_ih[orig] + b_hh[orig];
        g_b0[i] = b0;
        float be = b0;
#pragma unroll 4
        for (int j = 0; j < IND; j++) be += W_ih[orig * IND + j] * b_d[j];
        g_beff[i] = be;
    }
}

// prep_weff: W_eff = W_hh + W_ih @ W_d  (fp32 compute, fp16 store, reordered)
__global__ void prep_weff(const float* __restrict__ W_ih, const float* __restrict__ W_hh,
                          const float* __restrict__ W_d) {
    int i = blockIdx.x * blockDim.x + threadIdx.x;
    if (i >= GATES * UNITS) return;
    int rp = i / UNITS, k = i % UNITS;
    int orig = (rp & 3) * UNITS + (rp >> 2);
    float s = W_hh[orig * UNITS + k];
#pragma unroll 4
    for (int j = 0; j < IND; j++) s += W_ih[orig * IND + j] * W_d[j * UNITS + k];
    g_Weff[i] = __float2half_rn(s);
}

// prep_s: x0 (padded fp16), zero c.
__global__ void prep_s(const float* __restrict__ inputs) {
    int i = blockIdx.x * blockDim.x + threadIdx.x;
    if (i < BATCH * KP0) {
        int b = i / KP0, k = i % KP0;
        float v = (k < IND) ? inputs[(b * TIN + (TIN - 1)) * IND + k] : 0.0f;
        g_x0[i] = __float2half_rn(v);
    }
    if (i < BATCH * UNITS) g_c[i] = 0.0f;
}

// ---------------------------------------------------------------------------
// gates_t: fp16 mma.sync GEMM M=128,N=128,K=KP (f32 acc) + fused LSTM cell.
// FIRST: A = g_x0 (KP0), W = g_Wih16, bias = g_b0.
// else:  A = g_hist[s-1], W = g_Weff, bias = g_beff.
// h_s written to g_hist[s].
// ---------------------------------------------------------------------------
template<int KP>
__device__ __forceinline__ void load_stage_g(uint32_t sb, int stage, int kc, int tid,
                                             int bm0, int n0r,
                                             const __half* __restrict__ A,
                                             const __half* __restrict__ W) {
    uint32_t base = sb + stage * STG_STRIDE;
    int k0 = kc * 64;   // halves
#pragma unroll
    for (int i = 0; i < 4; i++) {
        int e = tid + i * 256;
        int row = e >> 3, sub = e & 7;
        uint32_t off = row * 128 + sub * 16;
        uint32_t sw = off ^ ((off >> 3) & 0x70);
        size_t gA = (size_t)(bm0 + row) * KP + k0 + sub * 8;
        cp16(base + T_AH + sw, A + gA);
        size_t gB = (size_t)(n0r + row) * KP + k0 + sub * 8;
        cp16(base + T_BH + sw, W + gB);
    }
    asm volatile("cp.async.commit_group;");
}

template<int NCH, int KP, bool FIRST>
__global__ __launch_bounds__(256) void gates_t(int s) {
    extern __shared__ __align__(1024) char smem[];
    const uint32_t sb = smem_u32(smem);
    float* sB = (float*)(smem + OFF_BIAS);
    const int tid = threadIdx.x;
    const int wid = tid >> 5;
    const int lane = tid & 31;
    const int bm0 = blockIdx.x * MT;
    const int nt  = blockIdx.y;
    const int n0r = nt * NTILE;

    const __half* __restrict__ A = FIRST ? g_x0
                                         : g_hist + (size_t)(s - 1) * BATCH * UNITS;
    const __half* __restrict__ W = FIRST ? g_Wih16 : g_Weff;
    const float*  __restrict__ bias = FIRST ? g_b0 : g_beff;
    __half* __restrict__ Hout = g_hist + (size_t)s * BATCH * UNITS;

    if (tid < NTILE) sB[tid] = bias[n0r + tid];

    // warp tiling: 2 (m) x 4 (n); warp tile 64 x 32
    const int wm = wid & 1, wn = wid >> 1;

    const int ra = lane & 7, qa = lane >> 3;
    const int colsel = (qa >> 1) * 16;
    int arow[4], axor[4], browr[2], bxor[2];
#pragma unroll
    for (int mi = 0; mi < 4; mi++) {
        int r = wm * 64 + mi * 16 + ra + (qa & 1) * 8;
        arow[mi] = r * 128;
        axor[mi] = (r & 7) << 4;
    }
#pragma unroll
    for (int nb = 0; nb < 2; nb++) {
        int r = wn * 32 + nb * 16 + ra + (qa & 1) * 8;
        browr[nb] = r * 128;
        bxor[nb] = (r & 7) << 4;
    }

    float acc[4][4][4];
#pragma unroll
    for (int mi = 0; mi < 4; mi++)
#pragma unroll
        for (int ni = 0; ni < 4; ni++)
#pragma unroll
            for (int j = 0; j < 4; j++) acc[mi][ni][j] = 0.0f;

    load_stage_g<KP>(sb, 0, 0, tid, bm0, n0r, A, W);
    load_stage_g<KP>(sb, 1, 1, tid, bm0, n0r, A, W);

#pragma unroll 1
    for (int i = 0; i < NCH; i++) {
        if (i + 2 < NCH) {
            load_stage_g<KP>(sb, (i + 2) % 3, i + 2, tid, bm0, n0r, A, W);
            asm volatile("cp.async.wait_group 2;");
        } else if (i + 1 < NCH) {
            asm volatile("cp.async.wait_group 1;");
        } else {
            asm volatile("cp.async.wait_group 0;");
        }
        __syncthreads();

        uint32_t base = sb + (i % 3) * STG_STRIDE;
#pragma unroll
        for (int kk = 0; kk < 4; kk++) {
            const int colb = kk * 32 + colsel;
            uint32_t ah[4][4], bh[2][4];
#pragma unroll
            for (int mi = 0; mi < 4; mi++)
                ldsm4(ah[mi], base + T_AH + arow[mi] + (colb ^ axor[mi]));
#pragma unroll
            for (int nb = 0; nb < 2; nb++)
                ldsm4(bh[nb], base + T_BH + browr[nb] + (colb ^ bxor[nb]));
#pragma unroll
            for (int mi = 0; mi < 4; mi++)
#pragma unroll
                for (int ni = 0; ni < 4; ni++) {
                    const int nb = ni >> 1, sE = ni & 1;
                    mma16816(acc[mi][ni], ah[mi], bh[nb][sE], bh[nb][sE + 2]);
                }
        }
        __syncthreads();
    }

    // ---- epilogue: frags -> smem, fused LSTM cell ----
    float* sC = (float*)smem;   // [128][132] = 67584 B < 98304
#pragma unroll
    for (int mi = 0; mi < 4; mi++)
#pragma unroll
        for (int ni = 0; ni < 4; ni++) {
            int r = wm * 64 + mi * 16 + (lane >> 2);
            int cidx = wn * 32 + ni * 8 + 2 * (lane & 3);
            sC[r * 132 + cidx]           = acc[mi][ni][0];
            sC[r * 132 + cidx + 1]       = acc[mi][ni][1];
            sC[(r + 8) * 132 + cidx]     = acc[mi][ni][2];
            sC[(r + 8) * 132 + cidx + 1] = acc[mi][ni][3];
        }
    __syncthreads();

#pragma unroll
    for (int it = 0; it < 16; it++) {
        int idx = tid + it * 256;
        int row = idx >> 5, ul = idx & 31;
        int m = bm0 + row, ug = nt * 32 + ul;
        float iv = sigm(sC[row * 132 + ul * 4 + 0] + sB[ul * 4 + 0]);
        float fv = sigm(sC[row * 132 + ul * 4 + 1] + sB[ul * 4 + 1]);
        float gv = tanhf(sC[row * 132 + ul * 4 + 2] + sB[ul * 4 + 2]);
        float ov = sigm(sC[row * 132 + ul * 4 + 3] + sB[ul * 4 + 3]);
        float cv = fv * g_c[m * UNITS + ug] + iv * gv;
        g_c[m * UNITS + ug] = cv;
        float hv = ov * tanhf(cv);
        Hout[(size_t)m * UNITS + ug] = __float2half_rn(hv);
    }
}

// ---------------------------------------------------------------------------
// pred_all: one batched GEMM over the whole h-history.
// Rows r = s*BATCH + b (131072 rows), N=96, K=768, single-pass fp16, f32 acc.
// out[b, s, n] = hist[s, b, :] @ W_d[n, :] + b_d[n]
// Grid: 1024 M-tiles of 128 rows (tiles never straddle an s boundary).
// ---------------------------------------------------------------------------
__device__ __forceinline__ void load_pstage(uint32_t sb, int stage, int c, int tid,
                                            size_t abase) {
    uint32_t base = sb + stage * PSTG;
    int k0 = c * 64;
#pragma unroll
    for (int i = 0; i < 4; i++) {      // A: 128 rows
        int e = tid + i * 256;
        int row = e >> 3, sub = e & 7;
        uint32_t off = row * 128 + sub * 16;
        uint32_t sw = off ^ ((off >> 3) & 0x70);
        cp16(base + P_A + sw, g_hist + abase + (size_t)row * UNITS + k0 + sub * 8);
    }
#pragma unroll
    for (int i = 0; i < 3; i++) {      // B: 96 rows
        int e = tid + i * 256;
        int row = e >> 3, sub = e & 7;
        uint32_t off = row * 128 + sub * 16;
        uint32_t sw = off ^ ((off >> 3) & 0x70);
        cp16(base + P_BH + sw, g_Pdh + (size_t)row * UNITS + k0 + sub * 8);
    }
    asm volatile("cp.async.commit_group;");
}

__global__ __launch_bounds__(256) void pred_all(float* __restrict__ out,
                                                const float* __restrict__ b_d) {
    extern __shared__ __align__(1024) char smem[];
    const uint32_t sb = smem_u32(smem);
    const int tid = threadIdx.x;
    const int wid = tid >> 5;
    const int lane = tid & 31;
    const int bm0 = blockIdx.x * MT;
    const size_t abase = (size_t)bm0 * UNITS;

    // warp tiling: 4 (m) x 2 (n); warp tile 32 x 48
    const int wm = wid & 3, wn = wid >> 2;

    const int ra = lane & 7, qa = lane >> 3;
    const int colsel = (qa >> 1) * 16;
    int arow[2], axor[2], browr[3], bxor[3];
#pragma unroll
    for (int mi = 0; mi < 2; mi++) {
        int r = wm * 32 + mi * 16 + ra + (qa & 1) * 8;
        arow[mi] = r * 128;
        axor[mi] = (r & 7) << 4;
    }
#pragma unroll
    for (int nb = 0; nb < 3; nb++) {
        int r = wn * 48 + nb * 16 + ra + (qa & 1) * 8;
        browr[nb] = r * 128;
        bxor[nb] = (r & 7) << 4;
    }

    float acc[2][6][4];
#pragma unroll
    for (int mi = 0; mi < 2; mi++)
#pragma unroll
        for (int nj = 0; nj < 6; nj++)
#pragma unroll
            for (int j = 0; j < 4; j++) acc[mi][nj][j] = 0.0f;

    load_pstage(sb, 0, 0, tid, abase);

    int stage = 0;
#pragma unroll 1
    for (int c = 0; c < NCH_MAIN; c++) {
        if (c + 1 < NCH_MAIN) {
            load_pstage(sb, stage ^ 1, c + 1, tid, abase);
            asm volatile("cp.async.wait_group 1;");
        } else {
            asm volatile("cp.async.wait_group 0;");
        }
        __syncthreads();

        uint32_t base = sb + stage * PSTG;
#pragma unroll
        for (int kk = 0; kk < 4; kk++) {
            const int colb = kk * 32 + colsel;
            uint32_t ah[2][4], bh[3][4];
#pragma unroll
            for (int mi = 0; mi < 2; mi++)
                ldsm4(ah[mi], base + P_A + arow[mi] + (colb ^ axor[mi]));
#pragma unroll
            for (int nb = 0; nb < 3; nb++)
                ldsm4(bh[nb], base + P_BH + browr[nb] + (colb ^ bxor[nb]));
#pragma unroll
            for (int mi = 0; mi < 2; mi++)
#pragma unroll
                for (int nj = 0; nj < 6; nj++) {
                    const int nb = nj >> 1, sE = nj & 1;
                    mma16816(acc[mi][nj], ah[mi], bh[nb][sE], bh[nb][sE + 2]);
                }
        }
        __syncthreads();
        stage ^= 1;
    }

    // epilogue: add bias, scatter to out[b, s, n]
#pragma unroll
    for (int mi = 0; mi < 2; mi++)
#pragma unroll
        for (int nj = 0; nj < 6; nj++) {
            int r0 = bm0 + wm * 32 + mi * 16 + (lane >> 2);
            int cidx = wn * 48 + nj * 8 + 2 * (lane & 3);
            float b0v = b_d[cidx], b1v = b_d[cidx + 1];
#pragma unroll
            for (int half8 = 0; half8 < 2; half8++) {
                int r = r0 + half8 * 8;
                int b = r & (BATCH - 1);
                int s = r >> 11;
                size_t o = ((size_t)b * STEPS + s) * IND + cidx;
                out[o]     = acc[mi][nj][half8 * 2 + 0] + b0v;
                out[o + 1] = acc[mi][nj][half8 * 2 + 1] + b1v;
            }
        }
}

// ---------------------------------------------------------------------------
// Inputs: inputs, W_ih, W_hh, b_ih, b_hh, W_d, b_d
// ---------------------------------------------------------------------------
extern "C" void kernel_launch(void* const* d_in, const int* in_sizes, int n_in,
                              void* d_out, int out_size) {
    const float* inputs = (const float*)d_in[0];
    const float* W_ih   = (const float*)d_in[1];
    const float* W_hh   = (const float*)d_in[2];
    const float* b_ih   = (const float*)d_in[3];
    const float* b_hh   = (const float*)d_in[4];
    const float* W_d    = (const float*)d_in[5];
    const float* b_d    = (const float*)d_in[6];
    float* out = (float*)d_out;

    cudaFuncSetAttribute(gates_t<NCH0, KP0, true>,
                         cudaFuncAttributeMaxDynamicSharedMemorySize, GATES_SMEM);
    cudaFuncSetAttribute(gates_t<NCH_MAIN, KP_MAIN, false>,
                         cudaFuncAttributeMaxDynamicSharedMemorySize, GATES_SMEM);
    cudaFuncSetAttribute(pred_all,
                         cudaFuncAttributeMaxDynamicSharedMemorySize, PRED_SMEM);

    prep_w<<<(GATES * KP0 + 255) / 256, 256>>>(W_ih, b_ih, b_hh, W_d, b_d);
    prep_weff<<<(GATES * UNITS + 255) / 256, 256>>>(W_ih, W_hh, W_d);
    prep_s<<<(BATCH * UNITS + 255) / 256, 256>>>(inputs);

    dim3 gg(MTILES, NTILES);   // 16 x 24 = 384 CTAs
    gates_t<NCH0, KP0, true><<<gg, 256, GATES_SMEM>>>(0);
    for (int s = 1; s < STEPS; s++)
        gates_t<NCH_MAIN, KP_MAIN, false><<<gg, 256, GATES_SMEM>>>(s);

    pred_all<<<(BATCH * STEPS) / MT, 256, PRED_SMEM>>>(out, b_d);
}

// round 10
// speedup vs baseline: 11.1534x; 1.3353x over previous
#include <cuda_runtime.h>
#include <cuda_fp16.h>
#include <cstdint>
#include <math.h>

#define BATCH 2048
#define UNITS 768
#define IND   96
#define GATES 3072
#define STEPS 64
#define TIN   24

#define MT 128
#define NTILE 128          /* 32 units x 4 gates (reorder r' = u*4+q) */
#define MTILES 16
#define NTILES 24
#define TILES_PER_STEP (MTILES * NTILES)        /* 384 */
#define TOTAL_TICKETS (STEPS * TILES_PER_STEP)  /* 24576 */
#define GRID_PERSIST 296

#define KP_MAIN 768        /* steps >= 1: K = UNITS */
#define NCH_MAIN 12
#define KP0 128            /* step 0: K = IND padded to 128 */
#define NCH0 2

/* gates smem: 3 stages x 32KB (A,B tiles of 16KB each) + bias */
#define STG_STRIDE 32768
#define T_AH 0
#define T_BH 16384
#define OFF_BIAS 98304
#define GATES_SMEM (OFF_BIAS + 512)     /* 98816 -> 2 CTAs/SM */

/* pred_all smem: 2 stages x 28KB (A 16KB + B 12KB) */
#define PSTG 28672
#define P_A  0
#define P_BH 16384
#define PRED_SMEM (2 * PSTG)            /* 57344 */

// ---------------------------------------------------------------------------
// Device globals
// ---------------------------------------------------------------------------
__device__ __half g_hist[(size_t)STEPS * BATCH * UNITS];  // h history
__device__ __half g_x0[BATCH * KP0];        // step-0 input, padded
__device__ float  g_c[BATCH * UNITS];       // cell state
__device__ __half g_Weff[GATES * UNITS];    // reordered W_hh + W_ih@W_d (fp16)
__device__ __half g_Wih16[GATES * KP0];     // reordered W_ih (fp16, padded)
__device__ __half g_Pdh[IND * UNITS];       // W_d fp16 (row n, col k)
__device__ float  g_b0[GATES];              // reordered b_ih + b_hh
__device__ float  g_beff[GATES];            // reordered b_ih + b_hh + W_ih@b_d
__device__ int    g_ticket;                 // global tile ticket
__device__ int    g_cnt[STEPS * MTILES];    // per-(step, m-block) completion

__device__ __forceinline__ uint32_t smem_u32(const void* p) {
    uint32_t a;
    asm("{ .reg .u64 t; cvta.to.shared.u64 t, %1; cvt.u32.u64 %0, t; }" : "=r"(a) : "l"(p));
    return a;
}
__device__ __forceinline__ void cp16(uint32_t dst, const void* src) {
    asm volatile("cp.async.cg.shared.global [%0], [%1], 16;" :: "r"(dst), "l"(src));
}
__device__ __forceinline__ void ldsm4(uint32_t* r, uint32_t addr) {
    asm volatile("ldmatrix.sync.aligned.m8n8.x4.shared.b16 {%0,%1,%2,%3}, [%4];"
        : "=r"(r[0]), "=r"(r[1]), "=r"(r[2]), "=r"(r[3]) : "r"(addr));
}
__device__ __forceinline__ void mma16816(float* c, const uint32_t* a, uint32_t b0, uint32_t b1) {
    asm volatile("mma.sync.aligned.m16n8k16.row.col.f32.f16.f16.f32 "
        "{%0,%1,%2,%3}, {%4,%5,%6,%7}, {%8,%9}, {%0,%1,%2,%3};"
        : "+f"(c[0]), "+f"(c[1]), "+f"(c[2]), "+f"(c[3])
        : "r"(a[0]), "r"(a[1]), "r"(a[2]), "r"(a[3]), "r"(b0), "r"(b1));
}
__device__ __forceinline__ float sigm(float x) { return 1.0f / (1.0f + expf(-x)); }

// ---------------------------------------------------------------------------
// prep kernels
// ---------------------------------------------------------------------------
__global__ void init_sched() {
    int i = blockIdx.x * blockDim.x + threadIdx.x;
    if (i == 0) g_ticket = 0;
    if (i < STEPS * MTILES) g_cnt[i] = 0;
}

__global__ void prep_w(const float* __restrict__ W_ih,
                       const float* __restrict__ b_ih, const float* __restrict__ b_hh,
                       const float* __restrict__ W_d, const float* __restrict__ b_d) {
    int i = blockIdx.x * blockDim.x + threadIdx.x;
    if (i < GATES * KP0) {
        int rp = i / KP0, k = i % KP0;
        int orig = (rp & 3) * UNITS + (rp >> 2);
        float w = (k < IND) ? W_ih[orig * IND + k] : 0.0f;
        g_Wih16[i] = __float2half_rn(w);
    }
    if (i < IND * UNITS) g_Pdh[i] = __float2half_rn(W_d[i]);
    if (i < GATES) {
        int orig = (i & 3) * UNITS + (i >> 2);
        float b0 = b_ih[orig] + b_hh[orig];
        g_b0[i] = b0;
        float be = b0;
#pragma unroll 4
        for (int j = 0; j < IND; j++) be += W_ih[orig * IND + j] * b_d[j];
        g_beff[i] = be;
    }
}

__global__ void prep_weff(const float* __restrict__ W_ih, const float* __restrict__ W_hh,
                          const float* __restrict__ W_d) {
    int i = blockIdx.x * blockDim.x + threadIdx.x;
    if (i >= GATES * UNITS) return;
    int rp = i / UNITS, k = i % UNITS;
    int orig = (rp & 3) * UNITS + (rp >> 2);
    float s = W_hh[orig * UNITS + k];
#pragma unroll 4
    for (int j = 0; j < IND; j++) s += W_ih[orig * IND + j] * W_d[j * UNITS + k];
    g_Weff[i] = __float2half_rn(s);
}

__global__ void prep_s(const float* __restrict__ inputs) {
    int i = blockIdx.x * blockDim.x + threadIdx.x;
    if (i < BATCH * KP0) {
        int b = i / KP0, k = i % KP0;
        float v = (k < IND) ? inputs[(b * TIN + (TIN - 1)) * IND + k] : 0.0f;
        g_x0[i] = __float2half_rn(v);
    }
    if (i < BATCH * UNITS) g_c[i] = 0.0f;
}

// ---------------------------------------------------------------------------
// gates_persist: persistent kernel, global ticket queue over all 64 steps.
// Ticket -> (s, m, nt). Tile (s,m,nt) waits until all 24 tiles (s-1, m, *)
// are complete (h[m-block] ready), enabling cross-step overlap.
// ---------------------------------------------------------------------------
__device__ __forceinline__ void load_stage_r(uint32_t sb, int stage, int kc, int tid,
                                             int bm0, int n0r, int kp,
                                             const __half* __restrict__ A,
                                             const __half* __restrict__ W) {
    uint32_t base = sb + stage * STG_STRIDE;
    int k0 = kc * 64;   // halves
#pragma unroll
    for (int i = 0; i < 4; i++) {
        int e = tid + i * 256;
        int row = e >> 3, sub = e & 7;
        uint32_t off = row * 128 + sub * 16;
        uint32_t sw = off ^ ((off >> 3) & 0x70);
        cp16(base + T_AH + sw, A + (size_t)(bm0 + row) * kp + k0 + sub * 8);
        cp16(base + T_BH + sw, W + (size_t)(n0r + row) * kp + k0 + sub * 8);
    }
    asm volatile("cp.async.commit_group;");
}

__global__ __launch_bounds__(256) void gates_persist() {
    extern __shared__ __align__(1024) char smem[];
    __shared__ int s_ticket;
    const uint32_t sb = smem_u32(smem);
    float* sB = (float*)(smem + OFF_BIAS);
    const int tid = threadIdx.x;
    const int wid = tid >> 5;
    const int lane = tid & 31;

    // warp tiling: 2 (m) x 4 (n); warp tile 64 x 32 (tile-independent setup)
    const int wm = wid & 1, wn = wid >> 1;
    const int ra = lane & 7, qa = lane >> 3;
    const int colsel = (qa >> 1) * 16;
    int arow[4], axor[4], browr[2], bxor[2];
#pragma unroll
    for (int mi = 0; mi < 4; mi++) {
        int r = wm * 64 + mi * 16 + ra + (qa & 1) * 8;
        arow[mi] = r * 128;
        axor[mi] = (r & 7) << 4;
    }
#pragma unroll
    for (int nb = 0; nb < 2; nb++) {
        int r = wn * 32 + nb * 16 + ra + (qa & 1) * 8;
        browr[nb] = r * 128;
        bxor[nb] = (r & 7) << 4;
    }

    for (;;) {
        if (tid == 0) s_ticket = atomicAdd(&g_ticket, 1);
        __syncthreads();
        const int ticket = s_ticket;
        if (ticket >= TOTAL_TICKETS) break;

        const int s  = ticket / TILES_PER_STEP;
        const int t  = ticket % TILES_PER_STEP;
        const int m  = t / NTILES;          // m-major: aligns with producers
        const int nt = t % NTILES;
        const int bm0 = m * MT;
        const int n0r = nt * NTILE;

        const __half* A; const __half* W; const float* bias;
        int kp, nch;
        if (s == 0) { A = g_x0; W = g_Wih16; bias = g_b0; kp = KP0; nch = NCH0; }
        else {
            A = g_hist + (size_t)(s - 1) * BATCH * UNITS;
            W = g_Weff; bias = g_beff; kp = KP_MAIN; nch = NCH_MAIN;
        }
        __half* __restrict__ Hout = g_hist + (size_t)s * BATCH * UNITS;

        // dependency: all 24 producers of h[s-1, m-block] complete
        if (s > 0) {
            if (tid == 0) {
                volatile int* c = &g_cnt[(s - 1) * MTILES + m];
                while (*c < NTILES) __nanosleep(64);
            }
            __syncthreads();
            __threadfence();   // acquire: h data visible before cp.async reads
        }

        if (tid < NTILE) sB[tid] = bias[n0r + tid];

        float acc[4][4][4];
#pragma unroll
        for (int mi = 0; mi < 4; mi++)
#pragma unroll
            for (int ni = 0; ni < 4; ni++)
#pragma unroll
                for (int j = 0; j < 4; j++) acc[mi][ni][j] = 0.0f;

        load_stage_r(sb, 0, 0, tid, bm0, n0r, kp, A, W);
        load_stage_r(sb, 1, 1, tid, bm0, n0r, kp, A, W);

#pragma unroll 1
        for (int i = 0; i < nch; i++) {
            if (i + 2 < nch) {
                load_stage_r(sb, (i + 2) % 3, i + 2, tid, bm0, n0r, kp, A, W);
                asm volatile("cp.async.wait_group 2;");
            } else if (i + 1 < nch) {
                asm volatile("cp.async.wait_group 1;");
            } else {
                asm volatile("cp.async.wait_group 0;");
            }
            __syncthreads();

            uint32_t base = sb + (i % 3) * STG_STRIDE;
#pragma unroll
            for (int kk = 0; kk < 4; kk++) {
                const int colb = kk * 32 + colsel;
                uint32_t ah[4][4], bh[2][4];
#pragma unroll
                for (int mi = 0; mi < 4; mi++)
                    ldsm4(ah[mi], base + T_AH + arow[mi] + (colb ^ axor[mi]));
#pragma unroll
                for (int nb = 0; nb < 2; nb++)
                    ldsm4(bh[nb], base + T_BH + browr[nb] + (colb ^ bxor[nb]));
#pragma unroll
                for (int mi = 0; mi < 4; mi++)
#pragma unroll
                    for (int ni = 0; ni < 4; ni++) {
                        const int nb = ni >> 1, sE = ni & 1;
                        mma16816(acc[mi][ni], ah[mi], bh[nb][sE], bh[nb][sE + 2]);
                    }
            }
            __syncthreads();
        }

        // ---- epilogue: frags -> smem, fused LSTM cell ----
        float* sC = (float*)smem;   // [128][132] = 67584 B < 98304
#pragma unroll
        for (int mi = 0; mi < 4; mi++)
#pragma unroll
            for (int ni = 0; ni < 4; ni++) {
                int r = wm * 64 + mi * 16 + (lane >> 2);
                int cidx = wn * 32 + ni * 8 + 2 * (lane & 3);
                sC[r * 132 + cidx]           = acc[mi][ni][0];
                sC[r * 132 + cidx + 1]       = acc[mi][ni][1];
                sC[(r + 8) * 132 + cidx]     = acc[mi][ni][2];
                sC[(r + 8) * 132 + cidx + 1] = acc[mi][ni][3];
            }
        __syncthreads();

#pragma unroll
        for (int it = 0; it < 16; it++) {
            int idx = tid + it * 256;
            int row = idx >> 5, ul = idx & 31;
            int mm = bm0 + row, ug = nt * 32 + ul;
            float iv = sigm(sC[row * 132 + ul * 4 + 0] + sB[ul * 4 + 0]);
            float fv = sigm(sC[row * 132 + ul * 4 + 1] + sB[ul * 4 + 1]);
            float gv = tanhf(sC[row * 132 + ul * 4 + 2] + sB[ul * 4 + 2]);
            float ov = sigm(sC[row * 132 + ul * 4 + 3] + sB[ul * 4 + 3]);
            float cv = fv * g_c[mm * UNITS + ug] + iv * gv;
            g_c[mm * UNITS + ug] = cv;
            float hv = ov * tanhf(cv);
            Hout[(size_t)mm * UNITS + ug] = __float2half_rn(hv);
        }

        __threadfence();        // release: publish h + c before counting
        __syncthreads();
        if (tid == 0) atomicAdd(&g_cnt[s * MTILES + m], 1);
    }
}

// ---------------------------------------------------------------------------
// pred_all: one batched GEMM over the whole h-history.
// Rows r = s*BATCH + b (131072 rows), N=96, K=768, single-pass fp16, f32 acc.
// ---------------------------------------------------------------------------
__device__ __forceinline__ void load_pstage(uint32_t sb, int stage, int c, int tid,
                                            size_t abase) {
    uint32_t base = sb + stage * PSTG;
    int k0 = c * 64;
#pragma unroll
    for (int i = 0; i < 4; i++) {      // A: 128 rows
        int e = tid + i * 256;
        int row = e >> 3, sub = e & 7;
        uint32_t off = row * 128 + sub * 16;
        uint32_t sw = off ^ ((off >> 3) & 0x70);
        cp16(base + P_A + sw, g_hist + abase + (size_t)row * UNITS + k0 + sub * 8);
    }
#pragma unroll
    for (int i = 0; i < 3; i++) {      // B: 96 rows
        int e = tid + i * 256;
        int row = e >> 3, sub = e & 7;
        uint32_t off = row * 128 + sub * 16;
        uint32_t sw = off ^ ((off >> 3) & 0x70);
        cp16(base + P_BH + sw, g_Pdh + (size_t)row * UNITS + k0 + sub * 8);
    }
    asm volatile("cp.async.commit_group;");
}

__global__ __launch_bounds__(256) void pred_all(float* __restrict__ out,
                                                const float* __restrict__ b_d) {
    extern __shared__ __align__(1024) char smem[];
    const uint32_t sb = smem_u32(smem);
    const int tid = threadIdx.x;
    const int wid = tid >> 5;
    const int lane = tid & 31;
    const int bm0 = blockIdx.x * MT;
    const size_t abase = (size_t)bm0 * UNITS;

    const int wm = wid & 3, wn = wid >> 2;
    const int ra = lane & 7, qa = lane >> 3;
    const int colsel = (qa >> 1) * 16;
    int arow[2], axor[2], browr[3], bxor[3];
#pragma unroll
    for (int mi = 0; mi < 2; mi++) {
        int r = wm * 32 + mi * 16 + ra + (qa & 1) * 8;
        arow[mi] = r * 128;
        axor[mi] = (r & 7) << 4;
    }
#pragma unroll
    for (int nb = 0; nb < 3; nb++) {
        int r = wn * 48 + nb * 16 + ra + (qa & 1) * 8;
        browr[nb] = r * 128;
        bxor[nb] = (r & 7) << 4;
    }

    float acc[2][6][4];
#pragma unroll
    for (int mi = 0; mi < 2; mi++)
#pragma unroll
        for (int nj = 0; nj < 6; nj++)
#pragma unroll
            for (int j = 0; j < 4; j++) acc[mi][nj][j] = 0.0f;

    load_pstage(sb, 0, 0, tid, abase);

    int stage = 0;
#pragma unroll 1
    for (int c = 0; c < NCH_MAIN; c++) {
        if (c + 1 < NCH_MAIN) {
            load_pstage(sb, stage ^ 1, c + 1, tid, abase);
            asm volatile("cp.async.wait_group 1;");
        } else {
            asm volatile("cp.async.wait_group 0;");
        }
        __syncthreads();

        uint32_t base = sb + stage * PSTG;
#pragma unroll
        for (int kk = 0; kk < 4; kk++) {
            const int colb = kk * 32 + colsel;
            uint32_t ah[2][4], bh[3][4];
#pragma unroll
            for (int mi = 0; mi < 2; mi++)
                ldsm4(ah[mi], base + P_A + arow[mi] + (colb ^ axor[mi]));
#pragma unroll
            for (int nb = 0; nb < 3; nb++)
                ldsm4(bh[nb], base + P_BH + browr[nb] + (colb ^ bxor[nb]));
#pragma unroll
            for (int mi = 0; mi < 2; mi++)
#pragma unroll
                for (int nj = 0; nj < 6; nj++) {
                    const int nb = nj >> 1, sE = nj & 1;
                    mma16816(acc[mi][nj], ah[mi], bh[nb][sE], bh[nb][sE + 2]);
                }
        }
        __syncthreads();
        stage ^= 1;
    }

#pragma unroll
    for (int mi = 0; mi < 2; mi++)
#pragma unroll
        for (int nj = 0; nj < 6; nj++) {
            int r0 = bm0 + wm * 32 + mi * 16 + (lane >> 2);
            int cidx = wn * 48 + nj * 8 + 2 * (lane & 3);
            float b0v = b_d[cidx], b1v = b_d[cidx + 1];
#pragma unroll
            for (int half8 = 0; half8 < 2; half8++) {
                int r = r0 + half8 * 8;
                int b = r & (BATCH - 1);
                int s = r >> 11;
                size_t o = ((size_t)b * STEPS + s) * IND + cidx;
                out[o]     = acc[mi][nj][half8 * 2 + 0] + b0v;
                out[o + 1] = acc[mi][nj][half8 * 2 + 1] + b1v;
            }
        }
}

// ---------------------------------------------------------------------------
// Inputs: inputs, W_ih, W_hh, b_ih, b_hh, W_d, b_d
// ---------------------------------------------------------------------------
extern "C" void kernel_launch(void* const* d_in, const int* in_sizes, int n_in,
                              void* d_out, int out_size) {
    const float* inputs = (const float*)d_in[0];
    const float* W_ih   = (const float*)d_in[1];
    const float* W_hh   = (const float*)d_in[2];
    const float* b_ih   = (const float*)d_in[3];
    const float* b_hh   = (const float*)d_in[4];
    const float* W_d    = (const float*)d_in[5];
    const float* b_d    = (const float*)d_in[6];
    float* out = (float*)d_out;

    cudaFuncSetAttribute(gates_persist,
                         cudaFuncAttributeMaxDynamicSharedMemorySize, GATES_SMEM);
    cudaFuncSetAttribute(pred_all,
                         cudaFuncAttributeMaxDynamicSharedMemorySize, PRED_SMEM);

    init_sched<<<(STEPS * MTILES + 255) / 256, 256>>>();
    prep_w<<<(GATES * KP0 + 255) / 256, 256>>>(W_ih, b_ih, b_hh, W_d, b_d);
    prep_weff<<<(GATES * UNITS + 255) / 256, 256>>>(W_ih, W_hh, W_d);
    prep_s<<<(BATCH * UNITS + 255) / 256, 256>>>(inputs);

    gates_persist<<<GRID_PERSIST, 256, GATES_SMEM>>>();

    pred_all<<<(BATCH * STEPS) / MT, 256, PRED_SMEM>>>(out, b_d);
}